// round 4
// baseline (speedup 1.0000x reference)
#include <cuda_runtime.h>

#define D_MODEL 1024
#define HEADS 16
#define DK 64
#define D_FF 4096
#define BATCH 2
#define SEQ 2048
#define NTOK (BATCH*SEQ)   // 4096

// ---------------- scratch (static device allocations; allowed) ----------------
__device__ float g_Wqkv[D_MODEL * 3 * D_MODEL];   // repacked [1024][3072]
__device__ float g_bqkv[3 * D_MODEL];
__device__ float g_qkv [NTOK * 3 * D_MODEL];      // QKV activations [4096][3072]
__device__ float g_ctx [NTOK * D_MODEL];          // attention context (heads concat)
__device__ float g_att [NTOK * D_MODEL];          // ctx @ Wo + bo
__device__ float g_h   [NTOK * D_MODEL];          // LN1 output
__device__ float g_ff1 [NTOK * D_FF];             // relu(h @ W1 + b1)
__device__ float g_ff2 [NTOK * D_MODEL];          // ff1 @ W2 + b2

// ---------------- repack per-head QKV weights into one [1024,3072] -------------
__global__ void repack_qkv(const float* __restrict__ Wq, const float* __restrict__ Wk,
                           const float* __restrict__ Wv, const float* __restrict__ bq,
                           const float* __restrict__ bk, const float* __restrict__ bv)
{
    int idx = blockIdx.x * blockDim.x + threadIdx.x;
    if (idx >= D_MODEL * 3 * D_MODEL) return;
    int d  = idx / (3 * D_MODEL);
    int n  = idx % (3 * D_MODEL);
    int pj = n / D_MODEL;          // 0=q 1=k 2=v
    int hk = n % D_MODEL;          // h*64 + k
    int h  = hk / DK;
    int k  = hk % DK;
    const float* W = (pj == 0) ? Wq : (pj == 1) ? Wk : Wv;
    g_Wqkv[idx] = W[(h * D_MODEL + d) * DK + k];
    if (idx < 3 * D_MODEL) {
        int p2 = idx / D_MODEL;
        int hk2 = idx % D_MODEL;
        const float* bb = (p2 == 0) ? bq : (p2 == 1) ? bk : bv;
        g_bqkv[idx] = bb[hk2];     // b[h][k] flattens to h*64+k directly
    }
}

// ---------------- 128x128x8 register-blocked SGEMM, C = A*B + bias (opt relu) ---
// A: [M,K] row-major   B: [K,N] row-major   C: [M,N] row-major
// M%128==0, N%128==0, K%8==0 (always true here) -> no bounds checks.
template<bool RELU>
__global__ __launch_bounds__(256) void gemm128(
    const float* __restrict__ A, const float* __restrict__ B,
    const float* __restrict__ bias, float* __restrict__ C,
    int M, int N, int K)
{
    const int BM = 128, BN = 128, BK = 8;
    __shared__ float As[BK][BM];
    __shared__ float Bs[BK][BN];

    int t  = threadIdx.x;
    int tr = t >> 4;          // 0..15 -> 8-row group
    int tc = t & 15;          // 0..15 -> 8-col group

    const float* Ab = A + (blockIdx.y * BM) * K;
    const float* Bb = B + blockIdx.x * BN;

    int arow = t >> 1, ac4 = (t & 1) * 4;     // A tile load: 128 rows x 8 cols
    int brow = t >> 5, bc4 = (t & 31) * 4;    // B tile load: 8 rows x 128 cols

    float acc[8][8];
    #pragma unroll
    for (int i = 0; i < 8; i++)
        #pragma unroll
        for (int j = 0; j < 8; j++) acc[i][j] = 0.f;

    for (int k0 = 0; k0 < K; k0 += BK) {
        float4 av = *(const float4*)(Ab + arow * K + k0 + ac4);
        As[ac4 + 0][arow] = av.x;
        As[ac4 + 1][arow] = av.y;
        As[ac4 + 2][arow] = av.z;
        As[ac4 + 3][arow] = av.w;
        *(float4*)&Bs[brow][bc4] = *(const float4*)(Bb + (k0 + brow) * N + bc4);
        __syncthreads();

        #pragma unroll
        for (int kk = 0; kk < BK; kk++) {
            float a[8], b[8];
            float4 a0 = *(const float4*)&As[kk][tr * 8];
            float4 a1 = *(const float4*)&As[kk][tr * 8 + 4];
            float4 b0 = *(const float4*)&Bs[kk][tc * 8];
            float4 b1 = *(const float4*)&Bs[kk][tc * 8 + 4];
            a[0]=a0.x; a[1]=a0.y; a[2]=a0.z; a[3]=a0.w;
            a[4]=a1.x; a[5]=a1.y; a[6]=a1.z; a[7]=a1.w;
            b[0]=b0.x; b[1]=b0.y; b[2]=b0.z; b[3]=b0.w;
            b[4]=b1.x; b[5]=b1.y; b[6]=b1.z; b[7]=b1.w;
            #pragma unroll
            for (int i = 0; i < 8; i++)
                #pragma unroll
                for (int j = 0; j < 8; j++)
                    acc[i][j] += a[i] * b[j];
        }
        __syncthreads();
    }

    #pragma unroll
    for (int i = 0; i < 8; i++) {
        int row = blockIdx.y * BM + tr * 8 + i;
        #pragma unroll
        for (int j4 = 0; j4 < 8; j4 += 4) {
            int col = blockIdx.x * BN + tc * 8 + j4;
            float4 v;
            v.x = acc[i][j4 + 0] + bias[col + 0];
            v.y = acc[i][j4 + 1] + bias[col + 1];
            v.z = acc[i][j4 + 2] + bias[col + 2];
            v.w = acc[i][j4 + 3] + bias[col + 3];
            if (RELU) {
                v.x = fmaxf(v.x, 0.f); v.y = fmaxf(v.y, 0.f);
                v.z = fmaxf(v.z, 0.f); v.w = fmaxf(v.w, 0.f);
            }
            *(float4*)(C + row * N + col) = v;
        }
    }
}

// ---------------- flash attention: 1 thread = 1 query row ----------------------
// grid: (SEQ/128, HEADS, BATCH), block: 128 threads
__global__ __launch_bounds__(128) void flash_attn(
    const float* __restrict__ qkv, const int* __restrict__ mask,
    float* __restrict__ ctx)
{
    const int BQ = 128, BKV = 64;
    int h = blockIdx.y, b = blockIdx.z;
    int t = threadIdx.x;
    int qrow = blockIdx.x * BQ + t;

    __shared__ float Ks[BKV][DK];
    __shared__ float Vs[BKV][DK];
    __shared__ float msk[BKV];

    const float scale = 0.125f;   // 1/sqrt(64)
    float q[DK];
    const float* qptr = qkv + (b * SEQ + qrow) * (3 * D_MODEL) + h * DK;
    #pragma unroll
    for (int d = 0; d < DK; d += 4) {
        float4 v = *(const float4*)(qptr + d);
        q[d+0] = v.x * scale; q[d+1] = v.y * scale;
        q[d+2] = v.z * scale; q[d+3] = v.w * scale;
    }

    float o[DK];
    #pragma unroll
    for (int d = 0; d < DK; d++) o[d] = 0.f;
    float m = -1e30f, l = 0.f;

    for (int kt = 0; kt < SEQ / BKV; kt++) {
        const float* kbase = qkv + (b * SEQ + kt * BKV) * (3 * D_MODEL) + D_MODEL + h * DK;
        const float* vbase = kbase + D_MODEL;
        #pragma unroll
        for (int i = 0; i < 8; i++) {
            int li = t * 8 + i;              // 0..1023
            int r  = li >> 4;                // 0..63
            int c4 = (li & 15) * 4;          // 0..60
            *(float4*)&Ks[r][c4] = *(const float4*)(kbase + r * (3 * D_MODEL) + c4);
            *(float4*)&Vs[r][c4] = *(const float4*)(vbase + r * (3 * D_MODEL) + c4);
        }
        if (t < BKV) msk[t] = mask[b * SEQ + kt * BKV + t] ? 0.f : -1e9f;
        __syncthreads();

        float s[BKV];
        float tilemax = -1e30f;
        #pragma unroll 4
        for (int j = 0; j < BKV; j++) {
            float acc = 0.f;
            #pragma unroll
            for (int d = 0; d < DK; d++) acc += q[d] * Ks[j][d];
            acc += msk[j];
            s[j] = acc;
            tilemax = fmaxf(tilemax, acc);
        }
        float newm = fmaxf(m, tilemax);
        float corr = __expf(m - newm);
        l *= corr;
        #pragma unroll
        for (int d = 0; d < DK; d++) o[d] *= corr;
        #pragma unroll 2
        for (int j = 0; j < BKV; j++) {
            float p = __expf(s[j] - newm);
            l += p;
            #pragma unroll
            for (int d = 0; d < DK; d++) o[d] += p * Vs[j][d];
        }
        m = newm;
        __syncthreads();
    }

    float inv = 1.f / l;
    float* optr = ctx + (b * SEQ + qrow) * D_MODEL + h * DK;
    #pragma unroll
    for (int d = 0; d < DK; d += 4) {
        float4 v;
        v.x = o[d+0] * inv; v.y = o[d+1] * inv;
        v.z = o[d+2] * inv; v.w = o[d+3] * inv;
        *(float4*)(optr + d) = v;
    }
}

// ---------------- out = LayerNorm(a + r) * g + beta ----------------------------
// grid: NTOK blocks, 256 threads; each thread owns 4 columns (t, t+256, ...)
__global__ __launch_bounds__(256) void add_ln(
    const float* __restrict__ a, const float* __restrict__ r,
    const float* __restrict__ g, const float* __restrict__ beta,
    float* __restrict__ out)
{
    int row = blockIdx.x;
    int t = threadIdx.x;
    __shared__ float red0[8], red1[8];

    const float* ap = a + row * D_MODEL;
    const float* rp = r + row * D_MODEL;
    float x[4];
    float s = 0.f, s2 = 0.f;
    #pragma unroll
    for (int i = 0; i < 4; i++) {
        int c = t + i * 256;
        x[i] = ap[c] + rp[c];
        s  += x[i];
        s2 += x[i] * x[i];
    }
    #pragma unroll
    for (int off = 16; off > 0; off >>= 1) {
        s  += __shfl_xor_sync(0xffffffffu, s,  off);
        s2 += __shfl_xor_sync(0xffffffffu, s2, off);
    }
    int wid = t >> 5;
    if ((t & 31) == 0) { red0[wid] = s; red1[wid] = s2; }
    __syncthreads();
    s = 0.f; s2 = 0.f;
    #pragma unroll
    for (int w = 0; w < 8; w++) { s += red0[w]; s2 += red1[w]; }

    float mean = s * (1.f / D_MODEL);
    float var  = s2 * (1.f / D_MODEL) - mean * mean;
    float inv  = rsqrtf(var + 1e-5f);
    #pragma unroll
    for (int i = 0; i < 4; i++) {
        int c = t + i * 256;
        out[row * D_MODEL + c] = (x[i] - mean) * inv * g[c] + beta[c];
    }
}

// ---------------- launch --------------------------------------------------------
extern "C" void kernel_launch(void* const* d_in, const int* in_sizes, int n_in,
                              void* d_out, int out_size)
{
    const float* x     = (const float*)d_in[0];
    const int*   mask  = (const int*)  d_in[1];
    const float* Wq    = (const float*)d_in[2];
    const float* bq    = (const float*)d_in[3];
    const float* Wk    = (const float*)d_in[4];
    const float* bk    = (const float*)d_in[5];
    const float* Wv    = (const float*)d_in[6];
    const float* bv    = (const float*)d_in[7];
    const float* Wo    = (const float*)d_in[8];
    const float* bo    = (const float*)d_in[9];
    const float* ln1_g = (const float*)d_in[10];
    const float* ln1_b = (const float*)d_in[11];
    const float* ln2_g = (const float*)d_in[12];
    const float* ln2_b = (const float*)d_in[13];
    const float* W1    = (const float*)d_in[14];
    const float* b1    = (const float*)d_in[15];
    const float* W2    = (const float*)d_in[16];
    const float* b2    = (const float*)d_in[17];

    float *pWqkv, *pbqkv, *pqkv, *pctx, *patt, *ph, *pff1, *pff2;
    cudaGetSymbolAddress((void**)&pWqkv, g_Wqkv);
    cudaGetSymbolAddress((void**)&pbqkv, g_bqkv);
    cudaGetSymbolAddress((void**)&pqkv,  g_qkv);
    cudaGetSymbolAddress((void**)&pctx,  g_ctx);
    cudaGetSymbolAddress((void**)&patt,  g_att);
    cudaGetSymbolAddress((void**)&ph,    g_h);
    cudaGetSymbolAddress((void**)&pff1,  g_ff1);
    cudaGetSymbolAddress((void**)&pff2,  g_ff2);

    // 1. repack QKV weights
    repack_qkv<<<(D_MODEL * 3 * D_MODEL + 255) / 256, 256>>>(Wq, Wk, Wv, bq, bk, bv);

    // 2. fused QKV projection: [4096,3072] = x[4096,1024] @ Wqkv[1024,3072]
    gemm128<false><<<dim3(3 * D_MODEL / 128, NTOK / 128), 256>>>(
        x, pWqkv, pbqkv, pqkv, NTOK, 3 * D_MODEL, D_MODEL);

    // 3. flash attention -> ctx [4096,1024] (heads concatenated)
    flash_attn<<<dim3(SEQ / 128, HEADS, BATCH), 128>>>(pqkv, mask, pctx);

    // 4. output projection
    gemm128<false><<<dim3(D_MODEL / 128, NTOK / 128), 256>>>(
        pctx, Wo, bo, patt, NTOK, D_MODEL, D_MODEL);

    // 5. h = LN(x + att)
    add_ln<<<NTOK, 256>>>(patt, x, ln1_g, ln1_b, ph);

    // 6. ff1 = relu(h @ W1 + b1)
    gemm128<true><<<dim3(D_FF / 128, NTOK / 128), 256>>>(
        ph, W1, b1, pff1, NTOK, D_FF, D_MODEL);

    // 7. ff2 = ff1 @ W2 + b2
    gemm128<false><<<dim3(D_MODEL / 128, NTOK / 128), 256>>>(
        pff1, W2, b2, pff2, NTOK, D_MODEL, D_FF);

    // 8. out = LN(h + ff2)
    add_ln<<<NTOK, 256>>>(pff2, ph, ln2_g, ln2_b, (float*)d_out);
}

// round 11
// speedup vs baseline: 1.4995x; 1.4995x over previous
#include <cuda_runtime.h>
#include <cuda_bf16.h>
#include <cstdint>

#define D_MODEL 1024
#define HEADS 16
#define DK 64
#define D_FF 4096
#define BATCH 2
#define SEQ 2048
#define NTOK (BATCH*SEQ)   // 4096

typedef __nv_bfloat16 bf16;

// ---------------- scratch ----------------
__device__ bf16  g_xhi [NTOK*D_MODEL],  g_xlo [NTOK*D_MODEL];
__device__ bf16  g_Wqkv_hi[3*D_MODEL*D_MODEL], g_Wqkv_lo[3*D_MODEL*D_MODEL]; // [3072][1024] (N,K)
__device__ float g_bqkv[3*D_MODEL];
__device__ float g_qkv [NTOK*3*D_MODEL];
__device__ bf16  g_ctxhi[NTOK*D_MODEL], g_ctxlo[NTOK*D_MODEL];
__device__ bf16  g_Wo_hi[D_MODEL*D_MODEL], g_Wo_lo[D_MODEL*D_MODEL];        // [1024][1024] (N,K)
__device__ float g_att[NTOK*D_MODEL];
__device__ float g_h  [NTOK*D_MODEL];
__device__ bf16  g_hhi[NTOK*D_MODEL], g_hlo[NTOK*D_MODEL];
__device__ bf16  g_W1_hi[D_FF*D_MODEL], g_W1_lo[D_FF*D_MODEL];              // [4096][1024]
__device__ bf16  g_W2_hi[D_MODEL*D_FF], g_W2_lo[D_MODEL*D_FF];              // [1024][4096]
__device__ bf16  g_ff1hi[NTOK*D_FF], g_ff1lo[NTOK*D_FF];
__device__ float g_ff2[NTOK*D_MODEL];

// ---------------- helpers ----------------
__device__ __forceinline__ uint32_t smem_u32(const void* p){
    uint32_t a;
    asm("{ .reg .u64 t; cvta.to.shared.u64 t, %1; cvt.u32.u64 %0, t; }" : "=r"(a) : "l"(p));
    return a;
}
__device__ __forceinline__ void f2hilo(float v, bf16& h, bf16& l){
    h = __float2bfloat16(v);
    l = __float2bfloat16(v - __bfloat162float(h));
}
__device__ __forceinline__ void ldsm4(uint32_t* r, uint32_t addr){
    asm volatile("ldmatrix.sync.aligned.m8n8.x4.shared.b16 {%0,%1,%2,%3}, [%4];"
        : "=r"(r[0]), "=r"(r[1]), "=r"(r[2]), "=r"(r[3]) : "r"(addr));
}
__device__ __forceinline__ void mma16816(float* c, const uint32_t* a, const uint32_t* b){
    asm volatile("mma.sync.aligned.m16n8k16.row.col.f32.bf16.bf16.f32 "
        "{%0,%1,%2,%3}, {%4,%5,%6,%7}, {%8,%9}, {%0,%1,%2,%3};"
        : "+f"(c[0]), "+f"(c[1]), "+f"(c[2]), "+f"(c[3])
        : "r"(a[0]), "r"(a[1]), "r"(a[2]), "r"(a[3]), "r"(b[0]), "r"(b[1]));
}
#define CPASYNC16(dst, src) asm volatile("cp.async.cg.shared.global [%0], [%1], 16;" :: "r"(dst), "l"(src))
#define CPCOMMIT()          asm volatile("cp.async.commit_group;" ::: "memory")
#define CPWAIT1()           asm volatile("cp.async.wait_group 1;" ::: "memory")

// ---------------- converts ----------------
__global__ void convert_x(const float* __restrict__ x, bf16* __restrict__ oh, bf16* __restrict__ ol, int n){
    int i = blockIdx.x * blockDim.x + threadIdx.x;
    if (i >= n) return;
    bf16 h, l; f2hilo(x[i], h, l);
    oh[i] = h; ol[i] = l;
}

__global__ void pack_qkv_w(const float* __restrict__ Wq, const float* __restrict__ Wk,
                           const float* __restrict__ Wv, const float* __restrict__ bq,
                           const float* __restrict__ bk, const float* __restrict__ bv)
{
    int idx = blockIdx.x * blockDim.x + threadIdx.x;
    if (idx >= 3 * D_MODEL * D_MODEL) return;
    int n = idx / D_MODEL;            // out row (q/k/v * 1024 + h*64+kk)
    int d = idx % D_MODEL;            // out col = input feature
    int pj = n >> 10, hh = (n & 1023) >> 6, kk = n & 63;
    const float* W = (pj == 0) ? Wq : (pj == 1) ? Wk : Wv;
    float v = W[(hh * D_MODEL + d) * DK + kk];
    bf16 h, l; f2hilo(v, h, l);
    g_Wqkv_hi[idx] = h; g_Wqkv_lo[idx] = l;
    if (idx < 3 * D_MODEL) {
        int p2 = idx / D_MODEL, hk2 = idx % D_MODEL;
        const float* bb = (p2 == 0) ? bq : (p2 == 1) ? bk : bv;
        g_bqkv[idx] = bb[hk2];
    }
}

// W[K,N] fp32 -> out[N,K] bf16 hi/lo (tiled transpose)
__global__ void tconv(const float* __restrict__ W, bf16* __restrict__ oh, bf16* __restrict__ ol, int K, int N){
    __shared__ float tile[32][33];
    int kx = blockIdx.y * 32 + threadIdx.y;
    int nx = blockIdx.x * 32 + threadIdx.x;
    tile[threadIdx.y][threadIdx.x] = W[(size_t)kx * N + nx];
    __syncthreads();
    int on = blockIdx.x * 32 + threadIdx.y;
    int ok = blockIdx.y * 32 + threadIdx.x;
    float v = tile[threadIdx.x][threadIdx.y];
    bf16 h, l; f2hilo(v, h, l);
    oh[(size_t)on * K + ok] = h; ol[(size_t)on * K + ok] = l;
}

// ---------------- HMMA split-bf16 GEMM ----------------
// C[M,N] = (Ahi+Alo)[M,K] @ (Bhi+Blo)[N,K]^T + bias   (drops lo*lo)
// CTA 128x128, BK=32, 8 warps (2x4 -> warp tile 64x32), 3-stage cp.async pipeline.
#define PITCH 80                       // 32 bf16 = 64B data + 16B pad (conflict-free ldmatrix)
#define ATILE (128*PITCH)              // 10240 B
#define STAGE (4*ATILE)                // Ahi,Alo,Bhi,Blo = 40960 B
#define NSTG 3
#define SMEM_GEMM (NSTG*STAGE)         // 122880 B

template<bool RELU, bool WF32, bool WHILO>
__global__ __launch_bounds__(256) void gemm_mma(
    const bf16* __restrict__ Ahi, const bf16* __restrict__ Alo,
    const bf16* __restrict__ Bhi, const bf16* __restrict__ Blo,
    const float* __restrict__ bias,
    float* __restrict__ Cf, bf16* __restrict__ Chi, bf16* __restrict__ Clo,
    int M, int N, int K)
{
    extern __shared__ char smem[];
    uint32_t sb = smem_u32(smem);
    int t = threadIdx.x, lane = t & 31, wid = t >> 5;
    int wm = wid >> 2, wn = wid & 3;                 // 2 x 4 warp grid
    int m0 = blockIdx.y * 128, n0 = blockIdx.x * 128;
    const int NC = K / 32;

    const bf16* gp0 = Ahi + (size_t)m0 * K;
    const bf16* gp1 = Alo + (size_t)m0 * K;
    const bf16* gp2 = Bhi + (size_t)n0 * K;
    const bf16* gp3 = Blo + (size_t)n0 * K;

    // ---- stage loader: 8 x 16B cp.async per thread ----
    auto load_stage = [&](int c){
        uint32_t st = sb + (c % NSTG) * STAGE;
        int k0 = c * 32;
        #pragma unroll
        for (int i = 0; i < 2; i++) {
            int idx = t + i * 256;                   // 0..511
            int row = idx >> 2, cc = idx & 3;        // 128 rows x 4 16B-chunks
            uint32_t d = st + row * PITCH + cc * 16;
            size_t g = (size_t)row * K + k0 + cc * 8;
            CPASYNC16(d,             gp0 + g);
            CPASYNC16(d + ATILE,     gp1 + g);
            CPASYNC16(d + 2*ATILE,   gp2 + g);
            CPASYNC16(d + 3*ATILE,   gp3 + g);
        }
    };

    float acc[4][4][4];
    #pragma unroll
    for (int i = 0; i < 4; i++)
        #pragma unroll
        for (int j = 0; j < 4; j++)
            #pragma unroll
            for (int q = 0; q < 4; q++) acc[i][j][q] = 0.f;

    load_stage(0); CPCOMMIT();
    load_stage(1); CPCOMMIT();

    // ldmatrix lane addressing (precomputed)
    int aRow  = lane & 15;
    int aColB = ((lane >> 4) & 1) * 16;
    int bRow  = ((lane >> 4) & 1) * 8 + (lane & 7);
    int bColB = ((lane >> 3) & 1) * 16;

    for (int c = 0; c < NC; c++) {
        if (c + 2 < NC) load_stage(c + 2);
        CPCOMMIT();
        CPWAIT1();
        __syncthreads();

        uint32_t st = sb + (c % NSTG) * STAGE;
        #pragma unroll
        for (int kc = 0; kc < 2; kc++) {
            uint32_t Afh[4][4], Afl[4][4];
            #pragma unroll
            for (int mt = 0; mt < 4; mt++) {
                uint32_t off = (uint32_t)((wm * 64 + mt * 16 + aRow) * PITCH + kc * 32 + aColB);
                ldsm4(Afh[mt], st + off);
                ldsm4(Afl[mt], st + ATILE + off);
            }
            uint32_t Bfh[4][2], Bfl[4][2];
            #pragma unroll
            for (int np = 0; np < 2; np++) {
                uint32_t off = (uint32_t)((wn * 32 + np * 16 + bRow) * PITCH + kc * 32 + bColB);
                uint32_t rh[4], rl[4];
                ldsm4(rh, st + 2*ATILE + off);
                ldsm4(rl, st + 3*ATILE + off);
                Bfh[np*2][0]=rh[0]; Bfh[np*2][1]=rh[1]; Bfh[np*2+1][0]=rh[2]; Bfh[np*2+1][1]=rh[3];
                Bfl[np*2][0]=rl[0]; Bfl[np*2][1]=rl[1]; Bfl[np*2+1][0]=rl[2]; Bfl[np*2+1][1]=rl[3];
            }
            #pragma unroll
            for (int mt = 0; mt < 4; mt++)
                #pragma unroll
                for (int nt = 0; nt < 4; nt++) {
                    float* cp = acc[mt][nt];
                    mma16816(cp, Afh[mt], Bfh[nt]);   // hi*hi
                    mma16816(cp, Afh[mt], Bfl[nt]);   // hi*lo
                    mma16816(cp, Afl[mt], Bfh[nt]);   // lo*hi
                }
        }
        __syncthreads();
    }

    // ---- epilogue ----
    int g = lane >> 2, tq = lane & 3;
    #pragma unroll
    for (int mt = 0; mt < 4; mt++) {
        int r0 = m0 + wm * 64 + mt * 16 + g;
        #pragma unroll
        for (int nt = 0; nt < 4; nt++) {
            int col = n0 + wn * 32 + nt * 8 + tq * 2;
            float b0 = bias[col], b1 = bias[col + 1];
            float v0 = acc[mt][nt][0] + b0;
            float v1 = acc[mt][nt][1] + b1;
            float v2 = acc[mt][nt][2] + b0;
            float v3 = acc[mt][nt][3] + b1;
            if (RELU) {
                v0 = fmaxf(v0, 0.f); v1 = fmaxf(v1, 0.f);
                v2 = fmaxf(v2, 0.f); v3 = fmaxf(v3, 0.f);
            }
            if (WF32) {
                float2 w0; w0.x = v0; w0.y = v1;
                float2 w1; w1.x = v2; w1.y = v3;
                *(float2*)(Cf + (size_t)r0 * N + col)       = w0;
                *(float2*)(Cf + (size_t)(r0 + 8) * N + col) = w1;
            }
            if (WHILO) {
                bf16 h0,h1,h2,h3,l0,l1,l2,l3;
                f2hilo(v0,h0,l0); f2hilo(v1,h1,l1); f2hilo(v2,h2,l2); f2hilo(v3,h3,l3);
                *(__nv_bfloat162*)(Chi + (size_t)r0 * N + col)       = __halves2bfloat162(h0, h1);
                *(__nv_bfloat162*)(Chi + (size_t)(r0 + 8) * N + col) = __halves2bfloat162(h2, h3);
                *(__nv_bfloat162*)(Clo + (size_t)r0 * N + col)       = __halves2bfloat162(l0, l1);
                *(__nv_bfloat162*)(Clo + (size_t)(r0 + 8) * N + col) = __halves2bfloat162(l2, l3);
            }
        }
    }
}

// ---------------- flash attention (hi/lo epilogue) -------------
__global__ __launch_bounds__(128) void flash_attn(
    const float* __restrict__ qkv, const int* __restrict__ mask,
    bf16* __restrict__ ctxhi, bf16* __restrict__ ctxlo)
{
    const int BQ = 128, BKV = 64;
    int hd = blockIdx.y, b = blockIdx.z;
    int t = threadIdx.x;
    int qrow = blockIdx.x * BQ + t;

    __shared__ float Ks[BKV][DK];
    __shared__ float Vs[BKV][DK];
    __shared__ float msk[BKV];

    const float scale = 0.125f;
    float q[DK];
    const float* qptr = qkv + (size_t)(b * SEQ + qrow) * (3 * D_MODEL) + hd * DK;
    #pragma unroll
    for (int d = 0; d < DK; d += 4) {
        float4 v = *(const float4*)(qptr + d);
        q[d+0] = v.x * scale; q[d+1] = v.y * scale;
        q[d+2] = v.z * scale; q[d+3] = v.w * scale;
    }
    float o[DK];
    #pragma unroll
    for (int d = 0; d < DK; d++) o[d] = 0.f;
    float m = -1e30f, l = 0.f;

    for (int kt = 0; kt < SEQ / BKV; kt++) {
        const float* kbase = qkv + (size_t)(b * SEQ + kt * BKV) * (3 * D_MODEL) + D_MODEL + hd * DK;
        const float* vbase = kbase + D_MODEL;
        #pragma unroll
        for (int i = 0; i < 8; i++) {
            int li = t * 8 + i;
            int r = li >> 4, c4 = (li & 15) * 4;
            *(float4*)&Ks[r][c4] = *(const float4*)(kbase + r * (3 * D_MODEL) + c4);
            *(float4*)&Vs[r][c4] = *(const float4*)(vbase + r * (3 * D_MODEL) + c4);
        }
        if (t < BKV) msk[t] = mask[b * SEQ + kt * BKV + t] ? 0.f : -1e9f;
        __syncthreads();

        float s[BKV];
        float tilemax = -1e30f;
        #pragma unroll 4
        for (int j = 0; j < BKV; j++) {
            float acc = 0.f;
            #pragma unroll
            for (int d = 0; d < DK; d++) acc += q[d] * Ks[j][d];
            acc += msk[j];
            s[j] = acc;
            tilemax = fmaxf(tilemax, acc);
        }
        float newm = fmaxf(m, tilemax);
        float corr = __expf(m - newm);
        l *= corr;
        #pragma unroll
        for (int d = 0; d < DK; d++) o[d] *= corr;
        #pragma unroll 2
        for (int j = 0; j < BKV; j++) {
            float p = __expf(s[j] - newm);
            l += p;
            #pragma unroll
            for (int d = 0; d < DK; d++) o[d] += p * Vs[j][d];
        }
        m = newm;
        __syncthreads();
    }

    float inv = 1.f / l;
    size_t ob = (size_t)(b * SEQ + qrow) * D_MODEL + hd * DK;
    #pragma unroll
    for (int d = 0; d < DK; d += 2) {
        bf16 h0, h1, l0, l1;
        f2hilo(o[d+0] * inv, h0, l0);
        f2hilo(o[d+1] * inv, h1, l1);
        *(__nv_bfloat162*)(ctxhi + ob + d) = __halves2bfloat162(h0, h1);
        *(__nv_bfloat162*)(ctxlo + ob + d) = __halves2bfloat162(l0, l1);
    }
}

// ---------------- out = LayerNorm(a + r); optionally also hi/lo ---------------
template<bool HILO>
__global__ __launch_bounds__(256) void add_ln(
    const float* __restrict__ a, const float* __restrict__ r,
    const float* __restrict__ g, const float* __restrict__ beta,
    float* __restrict__ out, bf16* __restrict__ ohi, bf16* __restrict__ olo)
{
    int row = blockIdx.x;
    int t = threadIdx.x;
    __shared__ float red0[8], red1[8];

    const float* ap = a + (size_t)row * D_MODEL;
    const float* rp = r + (size_t)row * D_MODEL;
    float x[4];
    float s = 0.f, s2 = 0.f;
    #pragma unroll
    for (int i = 0; i < 4; i++) {
        int c = t + i * 256;
        x[i] = ap[c] + rp[c];
        s += x[i]; s2 += x[i] * x[i];
    }
    #pragma unroll
    for (int off = 16; off > 0; off >>= 1) {
        s  += __shfl_xor_sync(0xffffffffu, s,  off);
        s2 += __shfl_xor_sync(0xffffffffu, s2, off);
    }
    int wid = t >> 5;
    if ((t & 31) == 0) { red0[wid] = s; red1[wid] = s2; }
    __syncthreads();
    s = 0.f; s2 = 0.f;
    #pragma unroll
    for (int w = 0; w < 8; w++) { s += red0[w]; s2 += red1[w]; }

    float mean = s * (1.f / D_MODEL);
    float var = s2 * (1.f / D_MODEL) - mean * mean;
    float inv = rsqrtf(var + 1e-5f);
    #pragma unroll
    for (int i = 0; i < 4; i++) {
        int c = t + i * 256;
        float y = (x[i] - mean) * inv * g[c] + beta[c];
        out[(size_t)row * D_MODEL + c] = y;
        if (HILO) {
            bf16 h, l; f2hilo(y, h, l);
            ohi[(size_t)row * D_MODEL + c] = h;
            olo[(size_t)row * D_MODEL + c] = l;
        }
    }
}

// ---------------- launch --------------------------------------------------------
extern "C" void kernel_launch(void* const* d_in, const int* in_sizes, int n_in,
                              void* d_out, int out_size)
{
    const float* x     = (const float*)d_in[0];
    const int*   mask  = (const int*)  d_in[1];
    const float* Wq    = (const float*)d_in[2];
    const float* bq    = (const float*)d_in[3];
    const float* Wk    = (const float*)d_in[4];
    const float* bk    = (const float*)d_in[5];
    const float* Wv    = (const float*)d_in[6];
    const float* bv    = (const float*)d_in[7];
    const float* Wo    = (const float*)d_in[8];
    const float* bo    = (const float*)d_in[9];
    const float* ln1_g = (const float*)d_in[10];
    const float* ln1_b = (const float*)d_in[11];
    const float* ln2_g = (const float*)d_in[12];
    const float* ln2_b = (const float*)d_in[13];
    const float* W1    = (const float*)d_in[14];
    const float* b1    = (const float*)d_in[15];
    const float* W2    = (const float*)d_in[16];
    const float* b2    = (const float*)d_in[17];

    bf16 *pxhi, *pxlo, *pWqh, *pWql, *pcxh, *pcxl, *pWoh, *pWol;
    bf16 *phhi, *phlo, *pW1h, *pW1l, *pW2h, *pW2l, *pf1h, *pf1l;
    float *pbqkv, *pqkv, *patt, *ph, *pff2;
    cudaGetSymbolAddress((void**)&pxhi, g_xhi);   cudaGetSymbolAddress((void**)&pxlo, g_xlo);
    cudaGetSymbolAddress((void**)&pWqh, g_Wqkv_hi); cudaGetSymbolAddress((void**)&pWql, g_Wqkv_lo);
    cudaGetSymbolAddress((void**)&pbqkv, g_bqkv); cudaGetSymbolAddress((void**)&pqkv, g_qkv);
    cudaGetSymbolAddress((void**)&pcxh, g_ctxhi); cudaGetSymbolAddress((void**)&pcxl, g_ctxlo);
    cudaGetSymbolAddress((void**)&pWoh, g_Wo_hi); cudaGetSymbolAddress((void**)&pWol, g_Wo_lo);
    cudaGetSymbolAddress((void**)&patt, g_att);   cudaGetSymbolAddress((void**)&ph, g_h);
    cudaGetSymbolAddress((void**)&phhi, g_hhi);   cudaGetSymbolAddress((void**)&phlo, g_hlo);
    cudaGetSymbolAddress((void**)&pW1h, g_W1_hi); cudaGetSymbolAddress((void**)&pW1l, g_W1_lo);
    cudaGetSymbolAddress((void**)&pW2h, g_W2_hi); cudaGetSymbolAddress((void**)&pW2l, g_W2_lo);
    cudaGetSymbolAddress((void**)&pf1h, g_ff1hi); cudaGetSymbolAddress((void**)&pf1l, g_ff1lo);
    cudaGetSymbolAddress((void**)&pff2, g_ff2);

    cudaFuncSetAttribute(gemm_mma<false, true, false>,
                         cudaFuncAttributeMaxDynamicSharedMemorySize, SMEM_GEMM);
    cudaFuncSetAttribute(gemm_mma<true, false, true>,
                         cudaFuncAttributeMaxDynamicSharedMemorySize, SMEM_GEMM);

    // weight/activation prep
    convert_x<<<(NTOK * D_MODEL + 255) / 256, 256>>>(x, pxhi, pxlo, NTOK * D_MODEL);
    pack_qkv_w<<<(3 * D_MODEL * D_MODEL + 255) / 256, 256>>>(Wq, Wk, Wv, bq, bk, bv);
    tconv<<<dim3(D_MODEL / 32, D_MODEL / 32), dim3(32, 32)>>>(Wo, pWoh, pWol, D_MODEL, D_MODEL);
    tconv<<<dim3(D_FF / 32,    D_MODEL / 32), dim3(32, 32)>>>(W1, pW1h, pW1l, D_MODEL, D_FF);
    tconv<<<dim3(D_MODEL / 32, D_FF / 32),    dim3(32, 32)>>>(W2, pW2h, pW2l, D_FF, D_MODEL);

    // qkv = x @ Wqkv + bqkv  (fp32 out)
    gemm_mma<false, true, false><<<dim3(3 * D_MODEL / 128, NTOK / 128), 256, SMEM_GEMM>>>(
        pxhi, pxlo, pWqh, pWql, pbqkv, pqkv, nullptr, nullptr, NTOK, 3 * D_MODEL, D_MODEL);

    // attention -> ctx hi/lo
    flash_attn<<<dim3(SEQ / 128, HEADS, BATCH), 128>>>(pqkv, mask, pcxh, pcxl);

    // att = ctx @ Wo + bo (fp32)
    gemm_mma<false, true, false><<<dim3(D_MODEL / 128, NTOK / 128), 256, SMEM_GEMM>>>(
        pcxh, pcxl, pWoh, pWol, bo, patt, nullptr, nullptr, NTOK, D_MODEL, D_MODEL);

    // h = LN(x + att)  (fp32 + hi/lo)
    add_ln<true><<<NTOK, 256>>>(patt, x, ln1_g, ln1_b, ph, phhi, phlo);

    // ff1 = relu(h @ W1 + b1)  (hi/lo only)
    gemm_mma<true, false, true><<<dim3(D_FF / 128, NTOK / 128), 256, SMEM_GEMM>>>(
        phhi, phlo, pW1h, pW1l, b1, nullptr, pf1h, pf1l, NTOK, D_FF, D_MODEL);

    // ff2 = ff1 @ W2 + b2 (fp32)
    gemm_mma<false, true, false><<<dim3(D_MODEL / 128, NTOK / 128), 256, SMEM_GEMM>>>(
        pf1h, pf1l, pW2h, pW2l, b2, pff2, nullptr, nullptr, NTOK, D_MODEL, D_FF);

    // out = LN(h + ff2)
    add_ln<false><<<NTOK, 256>>>(pff2, ph, ln2_g, ln2_b, (float*)d_out, nullptr, nullptr);
}

// round 12
// speedup vs baseline: 2.6827x; 1.7890x over previous
#include <cuda_runtime.h>
#include <cuda_bf16.h>
#include <cstdint>

#define D_MODEL 1024
#define HEADS 16
#define DK 64
#define D_FF 4096
#define BATCH 2
#define SEQ 2048
#define NTOK (BATCH*SEQ)   // 4096

typedef __nv_bfloat16 bf16;

// ---------------- scratch ----------------
__device__ bf16  g_xhi [NTOK*D_MODEL],  g_xlo [NTOK*D_MODEL];
__device__ bf16  g_Wqkv_hi[3*D_MODEL*D_MODEL], g_Wqkv_lo[3*D_MODEL*D_MODEL]; // [3072][1024] (N,K)
__device__ float g_bqkv[3*D_MODEL];
__device__ float g_qkv [NTOK*3*D_MODEL];
__device__ bf16  g_qh[NTOK*D_MODEL], g_ql[NTOK*D_MODEL];     // [b,h,s,dk] (scaled)
__device__ bf16  g_kh[NTOK*D_MODEL], g_kl[NTOK*D_MODEL];     // [b,h,s,dk]
__device__ bf16  g_vth[NTOK*D_MODEL], g_vtl[NTOK*D_MODEL];   // [b,h,dk,s]
__device__ bf16  g_ctxhi[NTOK*D_MODEL], g_ctxlo[NTOK*D_MODEL];
__device__ bf16  g_Wo_hi[D_MODEL*D_MODEL], g_Wo_lo[D_MODEL*D_MODEL];        // [1024][1024] (N,K)
__device__ float g_att[NTOK*D_MODEL];
__device__ float g_h  [NTOK*D_MODEL];
__device__ bf16  g_hhi[NTOK*D_MODEL], g_hlo[NTOK*D_MODEL];
__device__ bf16  g_W1_hi[D_FF*D_MODEL], g_W1_lo[D_FF*D_MODEL];              // [4096][1024]
__device__ bf16  g_W2_hi[D_MODEL*D_FF], g_W2_lo[D_MODEL*D_FF];              // [1024][4096]
__device__ bf16  g_ff1hi[NTOK*D_FF], g_ff1lo[NTOK*D_FF];
__device__ float g_ff2[NTOK*D_MODEL];

// ---------------- helpers ----------------
__device__ __forceinline__ uint32_t smem_u32(const void* p){
    uint32_t a;
    asm("{ .reg .u64 t; cvta.to.shared.u64 t, %1; cvt.u32.u64 %0, t; }" : "=r"(a) : "l"(p));
    return a;
}
__device__ __forceinline__ void f2hilo(float v, bf16& h, bf16& l){
    h = __float2bfloat16(v);
    l = __float2bfloat16(v - __bfloat162float(h));
}
__device__ __forceinline__ void ldsm4(uint32_t* r, uint32_t addr){
    asm volatile("ldmatrix.sync.aligned.m8n8.x4.shared.b16 {%0,%1,%2,%3}, [%4];"
        : "=r"(r[0]), "=r"(r[1]), "=r"(r[2]), "=r"(r[3]) : "r"(addr));
}
__device__ __forceinline__ void mma16816(float* c, const uint32_t* a, const uint32_t* b){
    asm volatile("mma.sync.aligned.m16n8k16.row.col.f32.bf16.bf16.f32 "
        "{%0,%1,%2,%3}, {%4,%5,%6,%7}, {%8,%9}, {%0,%1,%2,%3};"
        : "+f"(c[0]), "+f"(c[1]), "+f"(c[2]), "+f"(c[3])
        : "r"(a[0]), "r"(a[1]), "r"(a[2]), "r"(a[3]), "r"(b[0]), "r"(b[1]));
}
__device__ __forceinline__ void mma16816s(float* c, const uint32_t* a, uint32_t b0, uint32_t b1){
    asm volatile("mma.sync.aligned.m16n8k16.row.col.f32.bf16.bf16.f32 "
        "{%0,%1,%2,%3}, {%4,%5,%6,%7}, {%8,%9}, {%0,%1,%2,%3};"
        : "+f"(c[0]), "+f"(c[1]), "+f"(c[2]), "+f"(c[3])
        : "r"(a[0]), "r"(a[1]), "r"(a[2]), "r"(a[3]), "r"(b0), "r"(b1));
}
__device__ __forceinline__ uint32_t packbf2(float x, float y){
    __nv_bfloat162 v = __halves2bfloat162(__float2bfloat16(x), __float2bfloat16(y));
    return *reinterpret_cast<uint32_t*>(&v);
}
#define CPASYNC16(dst, src) asm volatile("cp.async.cg.shared.global [%0], [%1], 16;" :: "r"(dst), "l"(src))
#define CPCOMMIT()          asm volatile("cp.async.commit_group;" ::: "memory")
#define CPWAIT1()           asm volatile("cp.async.wait_group 1;" ::: "memory")

// ---------------- converts ----------------
__global__ void convert_x(const float* __restrict__ x, bf16* __restrict__ oh, bf16* __restrict__ ol, int n){
    int i = blockIdx.x * blockDim.x + threadIdx.x;
    if (i >= n) return;
    bf16 h, l; f2hilo(x[i], h, l);
    oh[i] = h; ol[i] = l;
}

__global__ void pack_qkv_w(const float* __restrict__ Wq, const float* __restrict__ Wk,
                           const float* __restrict__ Wv, const float* __restrict__ bq,
                           const float* __restrict__ bk, const float* __restrict__ bv)
{
    int idx = blockIdx.x * blockDim.x + threadIdx.x;
    if (idx >= 3 * D_MODEL * D_MODEL) return;
    int n = idx / D_MODEL;
    int d = idx % D_MODEL;
    int pj = n >> 10, hh = (n & 1023) >> 6, kk = n & 63;
    const float* W = (pj == 0) ? Wq : (pj == 1) ? Wk : Wv;
    float v = W[(hh * D_MODEL + d) * DK + kk];
    bf16 h, l; f2hilo(v, h, l);
    g_Wqkv_hi[idx] = h; g_Wqkv_lo[idx] = l;
    if (idx < 3 * D_MODEL) {
        int p2 = idx / D_MODEL, hk2 = idx % D_MODEL;
        const float* bb = (p2 == 0) ? bq : (p2 == 1) ? bk : bv;
        g_bqkv[idx] = bb[hk2];
    }
}

// W[K,N] fp32 -> out[N,K] bf16 hi/lo (tiled transpose)
__global__ void tconv(const float* __restrict__ W, bf16* __restrict__ oh, bf16* __restrict__ ol, int K, int N){
    __shared__ float tile[32][33];
    int kx = blockIdx.y * 32 + threadIdx.y;
    int nx = blockIdx.x * 32 + threadIdx.x;
    tile[threadIdx.y][threadIdx.x] = W[(size_t)kx * N + nx];
    __syncthreads();
    int on = blockIdx.x * 32 + threadIdx.y;
    int ok = blockIdx.y * 32 + threadIdx.x;
    float v = tile[threadIdx.x][threadIdx.y];
    bf16 h, l; f2hilo(v, h, l);
    oh[(size_t)on * K + ok] = h; ol[(size_t)on * K + ok] = l;
}

// ---------------- prep attention operands -------------------------------------
// qkv fp32 [tok][3072] -> Q(scaled)/K hi,lo [bh][s][64]; V^T hi,lo [bh][64][s]
__global__ void prep_attn(const float* __restrict__ qkv)
{
    __shared__ float vt[32][33];
    int bh = blockIdx.z;
    int b = bh / HEADS, hh = bh % HEADS;
    int s0 = blockIdx.x * 32, d0 = blockIdx.y * 32;
    int tx = threadIdx.x, ty = threadIdx.y;

    size_t src = ((size_t)(b * SEQ + s0 + ty)) * (3 * D_MODEL) + hh * DK + d0 + tx;
    float qv = qkv[src] * 0.125f;
    float kv = qkv[src + D_MODEL];
    float vv = qkv[src + 2 * D_MODEL];

    size_t qdst = ((size_t)bh * SEQ + s0 + ty) * DK + d0 + tx;
    bf16 h, l;
    f2hilo(qv, h, l); g_qh[qdst] = h; g_ql[qdst] = l;
    f2hilo(kv, h, l); g_kh[qdst] = h; g_kl[qdst] = l;

    vt[ty][tx] = vv;
    __syncthreads();
    float tv = vt[tx][ty];   // = V[s0+tx][d0+ty]
    size_t vdst = ((size_t)bh * DK + d0 + ty) * SEQ + s0 + tx;
    f2hilo(tv, h, l); g_vth[vdst] = h; g_vtl[vdst] = l;
}

// ---------------- HMMA split-bf16 GEMM (unchanged from round 11) ----------------
#define PITCH 80
#define ATILE (128*PITCH)
#define STAGE (4*ATILE)
#define NSTG 3
#define SMEM_GEMM (NSTG*STAGE)

template<bool RELU, bool WF32, bool WHILO>
__global__ __launch_bounds__(256) void gemm_mma(
    const bf16* __restrict__ Ahi, const bf16* __restrict__ Alo,
    const bf16* __restrict__ Bhi, const bf16* __restrict__ Blo,
    const float* __restrict__ bias,
    float* __restrict__ Cf, bf16* __restrict__ Chi, bf16* __restrict__ Clo,
    int M, int N, int K)
{
    extern __shared__ char smem[];
    uint32_t sb = smem_u32(smem);
    int t = threadIdx.x, lane = t & 31, wid = t >> 5;
    int wm = wid >> 2, wn = wid & 3;
    int m0 = blockIdx.y * 128, n0 = blockIdx.x * 128;
    const int NC = K / 32;

    const bf16* gp0 = Ahi + (size_t)m0 * K;
    const bf16* gp1 = Alo + (size_t)m0 * K;
    const bf16* gp2 = Bhi + (size_t)n0 * K;
    const bf16* gp3 = Blo + (size_t)n0 * K;

    auto load_stage = [&](int c){
        uint32_t st = sb + (c % NSTG) * STAGE;
        int k0 = c * 32;
        #pragma unroll
        for (int i = 0; i < 2; i++) {
            int idx = t + i * 256;
            int row = idx >> 2, cc = idx & 3;
            uint32_t d = st + row * PITCH + cc * 16;
            size_t g = (size_t)row * K + k0 + cc * 8;
            CPASYNC16(d,             gp0 + g);
            CPASYNC16(d + ATILE,     gp1 + g);
            CPASYNC16(d + 2*ATILE,   gp2 + g);
            CPASYNC16(d + 3*ATILE,   gp3 + g);
        }
    };

    float acc[4][4][4];
    #pragma unroll
    for (int i = 0; i < 4; i++)
        #pragma unroll
        for (int j = 0; j < 4; j++)
            #pragma unroll
            for (int q = 0; q < 4; q++) acc[i][j][q] = 0.f;

    load_stage(0); CPCOMMIT();
    load_stage(1); CPCOMMIT();

    int aRow  = lane & 15;
    int aColB = ((lane >> 4) & 1) * 16;
    int bRow  = ((lane >> 4) & 1) * 8 + (lane & 7);
    int bColB = ((lane >> 3) & 1) * 16;

    for (int c = 0; c < NC; c++) {
        if (c + 2 < NC) load_stage(c + 2);
        CPCOMMIT();
        CPWAIT1();
        __syncthreads();

        uint32_t st = sb + (c % NSTG) * STAGE;
        #pragma unroll
        for (int kc = 0; kc < 2; kc++) {
            uint32_t Afh[4][4], Afl[4][4];
            #pragma unroll
            for (int mt = 0; mt < 4; mt++) {
                uint32_t off = (uint32_t)((wm * 64 + mt * 16 + aRow) * PITCH + kc * 32 + aColB);
                ldsm4(Afh[mt], st + off);
                ldsm4(Afl[mt], st + ATILE + off);
            }
            uint32_t Bfh[4][2], Bfl[4][2];
            #pragma unroll
            for (int np = 0; np < 2; np++) {
                uint32_t off = (uint32_t)((wn * 32 + np * 16 + bRow) * PITCH + kc * 32 + bColB);
                uint32_t rh[4], rl[4];
                ldsm4(rh, st + 2*ATILE + off);
                ldsm4(rl, st + 3*ATILE + off);
                Bfh[np*2][0]=rh[0]; Bfh[np*2][1]=rh[1]; Bfh[np*2+1][0]=rh[2]; Bfh[np*2+1][1]=rh[3];
                Bfl[np*2][0]=rl[0]; Bfl[np*2][1]=rl[1]; Bfl[np*2+1][0]=rl[2]; Bfl[np*2+1][1]=rl[3];
            }
            #pragma unroll
            for (int mt = 0; mt < 4; mt++)
                #pragma unroll
                for (int nt = 0; nt < 4; nt++) {
                    float* cp = acc[mt][nt];
                    mma16816(cp, Afh[mt], Bfh[nt]);
                    mma16816(cp, Afh[mt], Bfl[nt]);
                    mma16816(cp, Afl[mt], Bfh[nt]);
                }
        }
        __syncthreads();
    }

    int g = lane >> 2, tq = lane & 3;
    #pragma unroll
    for (int mt = 0; mt < 4; mt++) {
        int r0 = m0 + wm * 64 + mt * 16 + g;
        #pragma unroll
        for (int nt = 0; nt < 4; nt++) {
            int col = n0 + wn * 32 + nt * 8 + tq * 2;
            float b0 = bias[col], b1 = bias[col + 1];
            float v0 = acc[mt][nt][0] + b0;
            float v1 = acc[mt][nt][1] + b1;
            float v2 = acc[mt][nt][2] + b0;
            float v3 = acc[mt][nt][3] + b1;
            if (RELU) {
                v0 = fmaxf(v0, 0.f); v1 = fmaxf(v1, 0.f);
                v2 = fmaxf(v2, 0.f); v3 = fmaxf(v3, 0.f);
            }
            if (WF32) {
                float2 w0; w0.x = v0; w0.y = v1;
                float2 w1; w1.x = v2; w1.y = v3;
                *(float2*)(Cf + (size_t)r0 * N + col)       = w0;
                *(float2*)(Cf + (size_t)(r0 + 8) * N + col) = w1;
            }
            if (WHILO) {
                bf16 h0,h1,h2,h3,l0,l1,l2,l3;
                f2hilo(v0,h0,l0); f2hilo(v1,h1,l1); f2hilo(v2,h2,l2); f2hilo(v3,h3,l3);
                *(__nv_bfloat162*)(Chi + (size_t)r0 * N + col)       = __halves2bfloat162(h0, h1);
                *(__nv_bfloat162*)(Chi + (size_t)(r0 + 8) * N + col) = __halves2bfloat162(h2, h3);
                *(__nv_bfloat162*)(Clo + (size_t)r0 * N + col)       = __halves2bfloat162(l0, l1);
                *(__nv_bfloat162*)(Clo + (size_t)(r0 + 8) * N + col) = __halves2bfloat162(l2, l3);
            }
        }
    }
}

// ---------------- HMMA flash attention -----------------------------------------
// grid (SEQ/64, HEADS, BATCH), 128 threads (4 warps); warp owns 16 q rows.
// smem: Q hi/lo (pitch 144) + 2-stage K hi/lo + Vt hi/lo + mask.
#define FP 144
#define FQT (64*FP)                   // 9216
#define FST0 (2*FQT)                  // 18432
#define FKH 0
#define FKL 9216
#define FVH 18432
#define FVL 27648
#define FMK 36864
#define FSSZ 37120
#define SMEM_FLASH (FST0 + 2*FSSZ)    // 92672

__global__ __launch_bounds__(128) void flash_mma(
    const bf16* __restrict__ Qh, const bf16* __restrict__ Ql,
    const bf16* __restrict__ Kh, const bf16* __restrict__ Kl,
    const bf16* __restrict__ Vth, const bf16* __restrict__ Vtl,
    const int* __restrict__ mask,
    bf16* __restrict__ ctxhi, bf16* __restrict__ ctxlo)
{
    extern __shared__ char smem[];
    uint32_t sb = smem_u32(smem);
    int t = threadIdx.x, lane = t & 31, w = t >> 5;
    int hh = blockIdx.y, b = blockIdx.z;
    int bh = b * HEADS + hh;
    int q0 = blockIdx.x * 64;
    const int NT = SEQ / 64;

    int aRow  = lane & 15;
    int aColB = ((lane >> 4) & 1) * 16;
    int bRow  = ((lane >> 4) & 1) * 8 + (lane & 7);
    int bColB = ((lane >> 3) & 1) * 16;

    // ---- Q tile load (once) ----
    {
        size_t qbase = ((size_t)bh * SEQ + q0) * DK;
        #pragma unroll
        for (int i = 0; i < 4; i++) {
            int idx = t + i * 128;            // 0..511
            int r = idx >> 3, ch = idx & 7;
            uint32_t d = sb + r * FP + ch * 16;
            size_t g = qbase + (size_t)r * DK + ch * 8;
            CPASYNC16(d,       Qh + g);
            CPASYNC16(d + FQT, Ql + g);
        }
    }
    auto load_stage = [&](int c){
        uint32_t st = sb + FST0 + (c & 1) * FSSZ;
        int kv0 = c * 64;
        size_t kbase = ((size_t)bh * SEQ + kv0) * DK;
        size_t vbase = (size_t)bh * DK * SEQ + kv0;
        #pragma unroll
        for (int i = 0; i < 4; i++) {
            int idx = t + i * 128;
            int r = idx >> 3, ch = idx & 7;
            uint32_t d = st + r * FP + ch * 16;
            CPASYNC16(d + FKH, Kh  + kbase + (size_t)r * DK + ch * 8);
            CPASYNC16(d + FKL, Kl  + kbase + (size_t)r * DK + ch * 8);
            CPASYNC16(d + FVH, Vth + vbase + (size_t)r * SEQ + ch * 8);
            CPASYNC16(d + FVL, Vtl + vbase + (size_t)r * SEQ + ch * 8);
        }
        if (t < 16) CPASYNC16(st + FMK + t * 16, mask + (size_t)b * SEQ + kv0 + t * 4);
    };

    load_stage(0); CPCOMMIT();
    load_stage(1); CPCOMMIT();

    uint32_t Qfh[4][4], Qfl[4][4];
    float oacc[8][4];
    #pragma unroll
    for (int i = 0; i < 8; i++)
        #pragma unroll
        for (int j = 0; j < 4; j++) oacc[i][j] = 0.f;
    float m0 = -1e30f, m1 = -1e30f, l0 = 0.f, l1 = 0.f;

    for (int c = 0; c < NT; c++) {
        CPWAIT1();
        __syncthreads();
        if (c == 0) {
            #pragma unroll
            for (int kc = 0; kc < 4; kc++) {
                uint32_t off = sb + (uint32_t)((w * 16 + aRow) * FP + kc * 32 + aColB);
                ldsm4(Qfh[kc], off);
                ldsm4(Qfl[kc], off + FQT);
            }
        }
        uint32_t st = sb + FST0 + (c & 1) * FSSZ;

        // ---- S = Q @ K^T (16x64 per warp) ----
        float sacc[8][4];
        #pragma unroll
        for (int i = 0; i < 8; i++)
            #pragma unroll
            for (int j = 0; j < 4; j++) sacc[i][j] = 0.f;
        #pragma unroll
        for (int kc = 0; kc < 4; kc++) {
            #pragma unroll
            for (int np = 0; np < 4; np++) {
                uint32_t off = (uint32_t)((np * 16 + bRow) * FP + kc * 32 + bColB);
                uint32_t rh[4], rl[4];
                ldsm4(rh, st + FKH + off);
                ldsm4(rl, st + FKL + off);
                mma16816s(sacc[2*np],   Qfh[kc], rh[0], rh[1]);
                mma16816s(sacc[2*np],   Qfh[kc], rl[0], rl[1]);
                mma16816s(sacc[2*np],   Qfl[kc], rh[0], rh[1]);
                mma16816s(sacc[2*np+1], Qfh[kc], rh[2], rh[3]);
                mma16816s(sacc[2*np+1], Qfh[kc], rl[2], rl[3]);
                mma16816s(sacc[2*np+1], Qfl[kc], rh[2], rh[3]);
            }
        }

        // ---- mask + online softmax ----
        const int* mk = (const int*)(smem + FST0 + (c & 1) * FSSZ + FMK);
        float mx0 = -1e30f, mx1 = -1e30f;
        #pragma unroll
        for (int nt = 0; nt < 8; nt++) {
            int col = nt * 8 + (lane & 3) * 2;
            float mv0 = mk[col]     ? 0.f : -1e9f;
            float mv1 = mk[col + 1] ? 0.f : -1e9f;
            sacc[nt][0] += mv0; sacc[nt][1] += mv1;
            sacc[nt][2] += mv0; sacc[nt][3] += mv1;
            mx0 = fmaxf(mx0, fmaxf(sacc[nt][0], sacc[nt][1]));
            mx1 = fmaxf(mx1, fmaxf(sacc[nt][2], sacc[nt][3]));
        }
        #pragma unroll
        for (int off = 1; off <= 2; off <<= 1) {
            mx0 = fmaxf(mx0, __shfl_xor_sync(0xffffffffu, mx0, off));
            mx1 = fmaxf(mx1, __shfl_xor_sync(0xffffffffu, mx1, off));
        }
        float nm0 = fmaxf(m0, mx0), nm1 = fmaxf(m1, mx1);
        float cr0 = __expf(m0 - nm0), cr1 = __expf(m1 - nm1);
        m0 = nm0; m1 = nm1;
        float rs0 = 0.f, rs1 = 0.f;
        #pragma unroll
        for (int nt = 0; nt < 8; nt++) {
            sacc[nt][0] = __expf(sacc[nt][0] - nm0);
            sacc[nt][1] = __expf(sacc[nt][1] - nm0);
            sacc[nt][2] = __expf(sacc[nt][2] - nm1);
            sacc[nt][3] = __expf(sacc[nt][3] - nm1);
            rs0 += sacc[nt][0] + sacc[nt][1];
            rs1 += sacc[nt][2] + sacc[nt][3];
            oacc[nt][0] *= cr0; oacc[nt][1] *= cr0;
            oacc[nt][2] *= cr1; oacc[nt][3] *= cr1;
        }
        #pragma unroll
        for (int off = 1; off <= 2; off <<= 1) {
            rs0 += __shfl_xor_sync(0xffffffffu, rs0, off);
            rs1 += __shfl_xor_sync(0xffffffffu, rs1, off);
        }
        l0 = l0 * cr0 + rs0;
        l1 = l1 * cr1 + rs1;

        // ---- P fragments (C-layout == A-layout identity) ----
        uint32_t Pah[4][4], Pal[4][4];
        #pragma unroll
        for (int kc = 0; kc < 4; kc++) {
            #pragma unroll
            for (int half = 0; half < 2; half++) {
                int nt = 2 * kc + half;
                float p0 = sacc[nt][0], p1 = sacc[nt][1];
                float p2 = sacc[nt][2], p3 = sacc[nt][3];
                bf16 h0 = __float2bfloat16(p0), h1 = __float2bfloat16(p1);
                bf16 h2 = __float2bfloat16(p2), h3 = __float2bfloat16(p3);
                Pah[kc][0 + 2*half] = *(uint32_t*)&(__nv_bfloat162&)*(__nv_bfloat162[]){__halves2bfloat162(h0, h1)};
                Pah[kc][1 + 2*half] = *(uint32_t*)&(__nv_bfloat162&)*(__nv_bfloat162[]){__halves2bfloat162(h2, h3)};
                Pal[kc][0 + 2*half] = packbf2(p0 - __bfloat162float(h0), p1 - __bfloat162float(h1));
                Pal[kc][1 + 2*half] = packbf2(p2 - __bfloat162float(h2), p3 - __bfloat162float(h3));
            }
        }

        // ---- O += P @ V (Vt rows = dk, cols = kv) ----
        #pragma unroll
        for (int kc = 0; kc < 4; kc++) {
            #pragma unroll
            for (int np = 0; np < 4; np++) {
                uint32_t off = (uint32_t)((np * 16 + bRow) * FP + kc * 32 + bColB);
                uint32_t vh[4], vl[4];
                ldsm4(vh, st + FVH + off);
                ldsm4(vl, st + FVL + off);
                mma16816s(oacc[2*np],   Pah[kc], vh[0], vh[1]);
                mma16816s(oacc[2*np],   Pah[kc], vl[0], vl[1]);
                mma16816s(oacc[2*np],   Pal[kc], vh[0], vh[1]);
                mma16816s(oacc[2*np+1], Pah[kc], vh[2], vh[3]);
                mma16816s(oacc[2*np+1], Pah[kc], vl[2], vl[3]);
                mma16816s(oacc[2*np+1], Pal[kc], vh[2], vh[3]);
            }
        }

        __syncthreads();
        if (c + 2 < NT) load_stage(c + 2);
        CPCOMMIT();
    }

    // ---- epilogue ----
    float inv0 = 1.f / l0, inv1 = 1.f / l1;
    int r0 = q0 + w * 16 + (lane >> 2);
    size_t tok0 = (size_t)b * SEQ + r0;
    #pragma unroll
    for (int nt = 0; nt < 8; nt++) {
        int col = hh * DK + nt * 8 + (lane & 3) * 2;
        bf16 h0, h1, h2, h3, e0, e1, e2, e3;
        f2hilo(oacc[nt][0] * inv0, h0, e0);
        f2hilo(oacc[nt][1] * inv0, h1, e1);
        f2hilo(oacc[nt][2] * inv1, h2, e2);
        f2hilo(oacc[nt][3] * inv1, h3, e3);
        *(__nv_bfloat162*)(ctxhi + tok0 * D_MODEL + col)       = __halves2bfloat162(h0, h1);
        *(__nv_bfloat162*)(ctxhi + (tok0 + 8) * D_MODEL + col) = __halves2bfloat162(h2, h3);
        *(__nv_bfloat162*)(ctxlo + tok0 * D_MODEL + col)       = __halves2bfloat162(e0, e1);
        *(__nv_bfloat162*)(ctxlo + (tok0 + 8) * D_MODEL + col) = __halves2bfloat162(e2, e3);
    }
}

// ---------------- out = LayerNorm(a + r); optionally also hi/lo ---------------
template<bool HILO>
__global__ __launch_bounds__(256) void add_ln(
    const float* __restrict__ a, const float* __restrict__ r,
    const float* __restrict__ g, const float* __restrict__ beta,
    float* __restrict__ out, bf16* __restrict__ ohi, bf16* __restrict__ olo)
{
    int row = blockIdx.x;
    int t = threadIdx.x;
    __shared__ float red0[8], red1[8];

    const float* ap = a + (size_t)row * D_MODEL;
    const float* rp = r + (size_t)row * D_MODEL;
    float x[4];
    float s = 0.f, s2 = 0.f;
    #pragma unroll
    for (int i = 0; i < 4; i++) {
        int c = t + i * 256;
        x[i] = ap[c] + rp[c];
        s += x[i]; s2 += x[i] * x[i];
    }
    #pragma unroll
    for (int off = 16; off > 0; off >>= 1) {
        s  += __shfl_xor_sync(0xffffffffu, s,  off);
        s2 += __shfl_xor_sync(0xffffffffu, s2, off);
    }
    int wid = t >> 5;
    if ((t & 31) == 0) { red0[wid] = s; red1[wid] = s2; }
    __syncthreads();
    s = 0.f; s2 = 0.f;
    #pragma unroll
    for (int w = 0; w < 8; w++) { s += red0[w]; s2 += red1[w]; }

    float mean = s * (1.f / D_MODEL);
    float var = s2 * (1.f / D_MODEL) - mean * mean;
    float inv = rsqrtf(var + 1e-5f);
    #pragma unroll
    for (int i = 0; i < 4; i++) {
        int c = t + i * 256;
        float y = (x[i] - mean) * inv * g[c] + beta[c];
        out[(size_t)row * D_MODEL + c] = y;
        if (HILO) {
            bf16 h, l; f2hilo(y, h, l);
            ohi[(size_t)row * D_MODEL + c] = h;
            olo[(size_t)row * D_MODEL + c] = l;
        }
    }
}

// ---------------- launch --------------------------------------------------------
extern "C" void kernel_launch(void* const* d_in, const int* in_sizes, int n_in,
                              void* d_out, int out_size)
{
    const float* x     = (const float*)d_in[0];
    const int*   mask  = (const int*)  d_in[1];
    const float* Wq    = (const float*)d_in[2];
    const float* bq    = (const float*)d_in[3];
    const float* Wk    = (const float*)d_in[4];
    const float* bk    = (const float*)d_in[5];
    const float* Wv    = (const float*)d_in[6];
    const float* bv    = (const float*)d_in[7];
    const float* Wo    = (const float*)d_in[8];
    const float* bo    = (const float*)d_in[9];
    const float* ln1_g = (const float*)d_in[10];
    const float* ln1_b = (const float*)d_in[11];
    const float* ln2_g = (const float*)d_in[12];
    const float* ln2_b = (const float*)d_in[13];
    const float* W1    = (const float*)d_in[14];
    const float* b1    = (const float*)d_in[15];
    const float* W2    = (const float*)d_in[16];
    const float* b2    = (const float*)d_in[17];

    bf16 *pxhi, *pxlo, *pWqh, *pWql, *pcxh, *pcxl, *pWoh, *pWol;
    bf16 *phhi, *phlo, *pW1h, *pW1l, *pW2h, *pW2l, *pf1h, *pf1l;
    bf16 *pqh, *pql, *pkh, *pkl, *pvth, *pvtl;
    float *pbqkv, *pqkv, *patt, *ph, *pff2;
    cudaGetSymbolAddress((void**)&pxhi, g_xhi);   cudaGetSymbolAddress((void**)&pxlo, g_xlo);
    cudaGetSymbolAddress((void**)&pWqh, g_Wqkv_hi); cudaGetSymbolAddress((void**)&pWql, g_Wqkv_lo);
    cudaGetSymbolAddress((void**)&pbqkv, g_bqkv); cudaGetSymbolAddress((void**)&pqkv, g_qkv);
    cudaGetSymbolAddress((void**)&pqh, g_qh);     cudaGetSymbolAddress((void**)&pql, g_ql);
    cudaGetSymbolAddress((void**)&pkh, g_kh);     cudaGetSymbolAddress((void**)&pkl, g_kl);
    cudaGetSymbolAddress((void**)&pvth, g_vth);   cudaGetSymbolAddress((void**)&pvtl, g_vtl);
    cudaGetSymbolAddress((void**)&pcxh, g_ctxhi); cudaGetSymbolAddress((void**)&pcxl, g_ctxlo);
    cudaGetSymbolAddress((void**)&pWoh, g_Wo_hi); cudaGetSymbolAddress((void**)&pWol, g_Wo_lo);
    cudaGetSymbolAddress((void**)&patt, g_att);   cudaGetSymbolAddress((void**)&ph, g_h);
    cudaGetSymbolAddress((void**)&phhi, g_hhi);   cudaGetSymbolAddress((void**)&phlo, g_hlo);
    cudaGetSymbolAddress((void**)&pW1h, g_W1_hi); cudaGetSymbolAddress((void**)&pW1l, g_W1_lo);
    cudaGetSymbolAddress((void**)&pW2h, g_W2_hi); cudaGetSymbolAddress((void**)&pW2l, g_W2_lo);
    cudaGetSymbolAddress((void**)&pf1h, g_ff1hi); cudaGetSymbolAddress((void**)&pf1l, g_ff1lo);
    cudaGetSymbolAddress((void**)&pff2, g_ff2);

    cudaFuncSetAttribute(gemm_mma<false, true, false>,
                         cudaFuncAttributeMaxDynamicSharedMemorySize, SMEM_GEMM);
    cudaFuncSetAttribute(gemm_mma<true, false, true>,
                         cudaFuncAttributeMaxDynamicSharedMemorySize, SMEM_GEMM);
    cudaFuncSetAttribute(flash_mma,
                         cudaFuncAttributeMaxDynamicSharedMemorySize, SMEM_FLASH);

    // weight/activation prep
    convert_x<<<(NTOK * D_MODEL + 255) / 256, 256>>>(x, pxhi, pxlo, NTOK * D_MODEL);
    pack_qkv_w<<<(3 * D_MODEL * D_MODEL + 255) / 256, 256>>>(Wq, Wk, Wv, bq, bk, bv);
    tconv<<<dim3(D_MODEL / 32, D_MODEL / 32), dim3(32, 32)>>>(Wo, pWoh, pWol, D_MODEL, D_MODEL);
    tconv<<<dim3(D_FF / 32,    D_MODEL / 32), dim3(32, 32)>>>(W1, pW1h, pW1l, D_MODEL, D_FF);
    tconv<<<dim3(D_MODEL / 32, D_FF / 32),    dim3(32, 32)>>>(W2, pW2h, pW2l, D_FF, D_MODEL);

    // qkv = x @ Wqkv + bqkv  (fp32 out)
    gemm_mma<false, true, false><<<dim3(3 * D_MODEL / 128, NTOK / 128), 256, SMEM_GEMM>>>(
        pxhi, pxlo, pWqh, pWql, pbqkv, pqkv, nullptr, nullptr, NTOK, 3 * D_MODEL, D_MODEL);

    // attention operand prep + HMMA flash attention -> ctx hi/lo
    prep_attn<<<dim3(SEQ / 32, DK / 32, BATCH * HEADS), dim3(32, 32)>>>(pqkv);
    flash_mma<<<dim3(SEQ / 64, HEADS, BATCH), 128, SMEM_FLASH>>>(
        pqh, pql, pkh, pkl, pvth, pvtl, mask, pcxh, pcxl);

    // att = ctx @ Wo + bo (fp32)
    gemm_mma<false, true, false><<<dim3(D_MODEL / 128, NTOK / 128), 256, SMEM_GEMM>>>(
        pcxh, pcxl, pWoh, pWol, bo, patt, nullptr, nullptr, NTOK, D_MODEL, D_MODEL);

    // h = LN(x + att)  (fp32 + hi/lo)
    add_ln<true><<<NTOK, 256>>>(patt, x, ln1_g, ln1_b, ph, phhi, phlo);

    // ff1 = relu(h @ W1 + b1)  (hi/lo only)
    gemm_mma<true, false, true><<<dim3(D_FF / 128, NTOK / 128), 256, SMEM_GEMM>>>(
        phhi, phlo, pW1h, pW1l, b1, nullptr, pf1h, pf1l, NTOK, D_FF, D_MODEL);

    // ff2 = ff1 @ W2 + b2 (fp32)
    gemm_mma<false, true, false><<<dim3(D_MODEL / 128, NTOK / 128), 256, SMEM_GEMM>>>(
        pf1h, pf1l, pW2h, pW2l, b2, pff2, nullptr, nullptr, NTOK, D_MODEL, D_FF);

    // out = LN(h + ff2)
    add_ln<false><<<NTOK, 256>>>(pff2, ph, ln2_g, ln2_b, (float*)d_out, nullptr, nullptr);
}

// round 15
// speedup vs baseline: 2.6872x; 1.0017x over previous
#include <cuda_runtime.h>
#include <cuda_bf16.h>
#include <cstdint>

#define D_MODEL 1024
#define HEADS 16
#define DK 64
#define D_FF 4096
#define BATCH 2
#define SEQ 2048
#define NTOK (BATCH*SEQ)   // 4096

typedef __nv_bfloat16 bf16;

// ---------------- scratch ----------------
__device__ bf16  g_xhi [NTOK*D_MODEL],  g_xlo [NTOK*D_MODEL];
__device__ bf16  g_Wqkv_hi[3*D_MODEL*D_MODEL], g_Wqkv_lo[3*D_MODEL*D_MODEL]; // [3072][1024] (N,K)
__device__ float g_bqkv[3*D_MODEL];
__device__ float g_qkv [NTOK*3*D_MODEL];
__device__ bf16  g_qh[NTOK*D_MODEL], g_ql[NTOK*D_MODEL];     // [b,h,s,dk] (scaled)
__device__ bf16  g_kh[NTOK*D_MODEL], g_kl[NTOK*D_MODEL];     // [b,h,s,dk]
__device__ bf16  g_vth[NTOK*D_MODEL], g_vtl[NTOK*D_MODEL];   // [b,h,dk,s]
__device__ bf16  g_ctxhi[NTOK*D_MODEL], g_ctxlo[NTOK*D_MODEL];
__device__ bf16  g_Wo_hi[D_MODEL*D_MODEL], g_Wo_lo[D_MODEL*D_MODEL];        // [1024][1024] (N,K)
__device__ float g_att[NTOK*D_MODEL];
__device__ float g_h  [NTOK*D_MODEL];
__device__ bf16  g_hhi[NTOK*D_MODEL], g_hlo[NTOK*D_MODEL];
__device__ bf16  g_W1_hi[D_FF*D_MODEL], g_W1_lo[D_FF*D_MODEL];              // [4096][1024]
__device__ bf16  g_W2_hi[D_MODEL*D_FF], g_W2_lo[D_MODEL*D_FF];              // [1024][4096]
__device__ bf16  g_ff1hi[NTOK*D_FF], g_ff1lo[NTOK*D_FF];
__device__ float g_ff2[NTOK*D_MODEL];

// ---------------- helpers ----------------
__device__ __forceinline__ uint32_t smem_u32(const void* p){
    uint32_t a;
    asm("{ .reg .u64 t; cvta.to.shared.u64 t, %1; cvt.u32.u64 %0, t; }" : "=r"(a) : "l"(p));
    return a;
}
__device__ __forceinline__ void f2hilo(float v, bf16& h, bf16& l){
    h = __float2bfloat16(v);
    l = __float2bfloat16(v - __bfloat162float(h));
}
__device__ __forceinline__ void ldsm4(uint32_t* r, uint32_t addr){
    asm volatile("ldmatrix.sync.aligned.m8n8.x4.shared.b16 {%0,%1,%2,%3}, [%4];"
        : "=r"(r[0]), "=r"(r[1]), "=r"(r[2]), "=r"(r[3]) : "r"(addr));
}
__device__ __forceinline__ void mma16816(float* c, const uint32_t* a, const uint32_t* b){
    asm volatile("mma.sync.aligned.m16n8k16.row.col.f32.bf16.bf16.f32 "
        "{%0,%1,%2,%3}, {%4,%5,%6,%7}, {%8,%9}, {%0,%1,%2,%3};"
        : "+f"(c[0]), "+f"(c[1]), "+f"(c[2]), "+f"(c[3])
        : "r"(a[0]), "r"(a[1]), "r"(a[2]), "r"(a[3]), "r"(b[0]), "r"(b[1]));
}
__device__ __forceinline__ void mma16816s(float* c, const uint32_t* a, uint32_t b0, uint32_t b1){
    asm volatile("mma.sync.aligned.m16n8k16.row.col.f32.bf16.bf16.f32 "
        "{%0,%1,%2,%3}, {%4,%5,%6,%7}, {%8,%9}, {%0,%1,%2,%3};"
        : "+f"(c[0]), "+f"(c[1]), "+f"(c[2]), "+f"(c[3])
        : "r"(a[0]), "r"(a[1]), "r"(a[2]), "r"(a[3]), "r"(b0), "r"(b1));
}
__device__ __forceinline__ uint32_t packbf2(float x, float y){
    __nv_bfloat162 v = __halves2bfloat162(__float2bfloat16(x), __float2bfloat16(y));
    return *reinterpret_cast<uint32_t*>(&v);
}
#define CPASYNC16(dst, src) asm volatile("cp.async.cg.shared.global [%0], [%1], 16;" :: "r"(dst), "l"(src))
#define CPCOMMIT()          asm volatile("cp.async.commit_group;" ::: "memory")
#define CPWAIT1()           asm volatile("cp.async.wait_group 1;" ::: "memory")

// ---------------- converts ----------------
__global__ void convert_x(const float* __restrict__ x, bf16* __restrict__ oh, bf16* __restrict__ ol, int n){
    int i = blockIdx.x * blockDim.x + threadIdx.x;
    if (i >= n) return;
    bf16 h, l; f2hilo(x[i], h, l);
    oh[i] = h; ol[i] = l;
}

__global__ void pack_qkv_w(const float* __restrict__ Wq, const float* __restrict__ Wk,
                           const float* __restrict__ Wv, const float* __restrict__ bq,
                           const float* __restrict__ bk, const float* __restrict__ bv)
{
    int idx = blockIdx.x * blockDim.x + threadIdx.x;
    if (idx >= 3 * D_MODEL * D_MODEL) return;
    int n = idx / D_MODEL;
    int d = idx % D_MODEL;
    int pj = n >> 10, hh = (n & 1023) >> 6, kk = n & 63;
    const float* W = (pj == 0) ? Wq : (pj == 1) ? Wk : Wv;
    float v = W[(hh * D_MODEL + d) * DK + kk];
    bf16 h, l; f2hilo(v, h, l);
    g_Wqkv_hi[idx] = h; g_Wqkv_lo[idx] = l;
    if (idx < 3 * D_MODEL) {
        int p2 = idx / D_MODEL, hk2 = idx % D_MODEL;
        const float* bb = (p2 == 0) ? bq : (p2 == 1) ? bk : bv;
        g_bqkv[idx] = bb[hk2];
    }
}

// W[K,N] fp32 -> out[N,K] bf16 hi/lo (tiled transpose)
__global__ void tconv(const float* __restrict__ W, bf16* __restrict__ oh, bf16* __restrict__ ol, int K, int N){
    __shared__ float tile[32][33];
    int kx = blockIdx.y * 32 + threadIdx.y;
    int nx = blockIdx.x * 32 + threadIdx.x;
    tile[threadIdx.y][threadIdx.x] = W[(size_t)kx * N + nx];
    __syncthreads();
    int on = blockIdx.x * 32 + threadIdx.y;
    int ok = blockIdx.y * 32 + threadIdx.x;
    float v = tile[threadIdx.x][threadIdx.y];
    bf16 h, l; f2hilo(v, h, l);
    oh[(size_t)on * K + ok] = h; ol[(size_t)on * K + ok] = l;
}

// ---------------- prep attention operands -------------------------------------
// qkv fp32 [tok][3072] -> Q(scaled)/K hi,lo [bh][s][64]; V^T hi,lo [bh][64][s]
__global__ void prep_attn(const float* __restrict__ qkv)
{
    __shared__ float vt[32][33];
    int bh = blockIdx.z;
    int b = bh / HEADS, hh = bh % HEADS;
    int s0 = blockIdx.x * 32, d0 = blockIdx.y * 32;
    int tx = threadIdx.x, ty = threadIdx.y;

    size_t src = ((size_t)(b * SEQ + s0 + ty)) * (3 * D_MODEL) + hh * DK + d0 + tx;
    float qv = qkv[src] * 0.125f;
    float kv = qkv[src + D_MODEL];
    float vv = qkv[src + 2 * D_MODEL];

    size_t qdst = ((size_t)bh * SEQ + s0 + ty) * DK + d0 + tx;
    bf16 h, l;
    f2hilo(qv, h, l); g_qh[qdst] = h; g_ql[qdst] = l;
    f2hilo(kv, h, l); g_kh[qdst] = h; g_kl[qdst] = l;

    vt[ty][tx] = vv;
    __syncthreads();
    float tv = vt[tx][ty];   // = V[s0+tx][d0+ty]
    size_t vdst = ((size_t)bh * DK + d0 + ty) * SEQ + s0 + tx;
    f2hilo(tv, h, l); g_vth[vdst] = h; g_vtl[vdst] = l;
}

// ---------------- HMMA split-bf16 GEMM (unchanged from round 11) ----------------
#define PITCH 80
#define ATILE (128*PITCH)
#define STAGE (4*ATILE)
#define NSTG 3
#define SMEM_GEMM (NSTG*STAGE)

template<bool RELU, bool WF32, bool WHILO>
__global__ __launch_bounds__(256) void gemm_mma(
    const bf16* __restrict__ Ahi, const bf16* __restrict__ Alo,
    const bf16* __restrict__ Bhi, const bf16* __restrict__ Blo,
    const float* __restrict__ bias,
    float* __restrict__ Cf, bf16* __restrict__ Chi, bf16* __restrict__ Clo,
    int M, int N, int K)
{
    extern __shared__ char smem[];
    uint32_t sb = smem_u32(smem);
    int t = threadIdx.x, lane = t & 31, wid = t >> 5;
    int wm = wid >> 2, wn = wid & 3;
    int m0 = blockIdx.y * 128, n0 = blockIdx.x * 128;
    const int NC = K / 32;

    const bf16* gp0 = Ahi + (size_t)m0 * K;
    const bf16* gp1 = Alo + (size_t)m0 * K;
    const bf16* gp2 = Bhi + (size_t)n0 * K;
    const bf16* gp3 = Blo + (size_t)n0 * K;

    auto load_stage = [&](int c){
        uint32_t st = sb + (c % NSTG) * STAGE;
        int k0 = c * 32;
        #pragma unroll
        for (int i = 0; i < 2; i++) {
            int idx = t + i * 256;
            int row = idx >> 2, cc = idx & 3;
            uint32_t d = st + row * PITCH + cc * 16;
            size_t g = (size_t)row * K + k0 + cc * 8;
            CPASYNC16(d,             gp0 + g);
            CPASYNC16(d + ATILE,     gp1 + g);
            CPASYNC16(d + 2*ATILE,   gp2 + g);
            CPASYNC16(d + 3*ATILE,   gp3 + g);
        }
    };

    float acc[4][4][4];
    #pragma unroll
    for (int i = 0; i < 4; i++)
        #pragma unroll
        for (int j = 0; j < 4; j++)
            #pragma unroll
            for (int q = 0; q < 4; q++) acc[i][j][q] = 0.f;

    load_stage(0); CPCOMMIT();
    load_stage(1); CPCOMMIT();

    int aRow  = lane & 15;
    int aColB = ((lane >> 4) & 1) * 16;
    int bRow  = ((lane >> 4) & 1) * 8 + (lane & 7);
    int bColB = ((lane >> 3) & 1) * 16;

    for (int c = 0; c < NC; c++) {
        if (c + 2 < NC) load_stage(c + 2);
        CPCOMMIT();
        CPWAIT1();
        __syncthreads();

        uint32_t st = sb + (c % NSTG) * STAGE;
        #pragma unroll
        for (int kc = 0; kc < 2; kc++) {
            uint32_t Afh[4][4], Afl[4][4];
            #pragma unroll
            for (int mt = 0; mt < 4; mt++) {
                uint32_t off = (uint32_t)((wm * 64 + mt * 16 + aRow) * PITCH + kc * 32 + aColB);
                ldsm4(Afh[mt], st + off);
                ldsm4(Afl[mt], st + ATILE + off);
            }
            uint32_t Bfh[4][2], Bfl[4][2];
            #pragma unroll
            for (int np = 0; np < 2; np++) {
                uint32_t off = (uint32_t)((wn * 32 + np * 16 + bRow) * PITCH + kc * 32 + bColB);
                uint32_t rh[4], rl[4];
                ldsm4(rh, st + 2*ATILE + off);
                ldsm4(rl, st + 3*ATILE + off);
                Bfh[np*2][0]=rh[0]; Bfh[np*2][1]=rh[1]; Bfh[np*2+1][0]=rh[2]; Bfh[np*2+1][1]=rh[3];
                Bfl[np*2][0]=rl[0]; Bfl[np*2][1]=rl[1]; Bfl[np*2+1][0]=rl[2]; Bfl[np*2+1][1]=rl[3];
            }
            #pragma unroll
            for (int mt = 0; mt < 4; mt++)
                #pragma unroll
                for (int nt = 0; nt < 4; nt++) {
                    float* cp = acc[mt][nt];
                    mma16816(cp, Afh[mt], Bfh[nt]);
                    mma16816(cp, Afh[mt], Bfl[nt]);
                    mma16816(cp, Afl[mt], Bfh[nt]);
                }
        }
        __syncthreads();
    }

    int g = lane >> 2, tq = lane & 3;
    #pragma unroll
    for (int mt = 0; mt < 4; mt++) {
        int r0 = m0 + wm * 64 + mt * 16 + g;
        #pragma unroll
        for (int nt = 0; nt < 4; nt++) {
            int col = n0 + wn * 32 + nt * 8 + tq * 2;
            float b0 = bias[col], b1 = bias[col + 1];
            float v0 = acc[mt][nt][0] + b0;
            float v1 = acc[mt][nt][1] + b1;
            float v2 = acc[mt][nt][2] + b0;
            float v3 = acc[mt][nt][3] + b1;
            if (RELU) {
                v0 = fmaxf(v0, 0.f); v1 = fmaxf(v1, 0.f);
                v2 = fmaxf(v2, 0.f); v3 = fmaxf(v3, 0.f);
            }
            if (WF32) {
                float2 w0; w0.x = v0; w0.y = v1;
                float2 w1; w1.x = v2; w1.y = v3;
                *(float2*)(Cf + (size_t)r0 * N + col)       = w0;
                *(float2*)(Cf + (size_t)(r0 + 8) * N + col) = w1;
            }
            if (WHILO) {
                bf16 h0,h1,h2,h3,l0,l1,l2,l3;
                f2hilo(v0,h0,l0); f2hilo(v1,h1,l1); f2hilo(v2,h2,l2); f2hilo(v3,h3,l3);
                *(__nv_bfloat162*)(Chi + (size_t)r0 * N + col)       = __halves2bfloat162(h0, h1);
                *(__nv_bfloat162*)(Chi + (size_t)(r0 + 8) * N + col) = __halves2bfloat162(h2, h3);
                *(__nv_bfloat162*)(Clo + (size_t)r0 * N + col)       = __halves2bfloat162(l0, l1);
                *(__nv_bfloat162*)(Clo + (size_t)(r0 + 8) * N + col) = __halves2bfloat162(l2, l3);
            }
        }
    }
}

// ---------------- HMMA flash attention -----------------------------------------
// grid (SEQ/64, HEADS, BATCH), 128 threads (4 warps); warp owns 16 q rows.
// smem: Q hi/lo (pitch 144) + 2-stage K hi/lo + Vt hi/lo + mask.
#define FP 144
#define FQT (64*FP)                   // 9216
#define FST0 (2*FQT)                  // 18432
#define FKH 0
#define FKL 9216
#define FVH 18432
#define FVL 27648
#define FMK 36864
#define FSSZ 37120
#define SMEM_FLASH (FST0 + 2*FSSZ)    // 92672

__global__ __launch_bounds__(128) void flash_mma(
    const bf16* __restrict__ Qh, const bf16* __restrict__ Ql,
    const bf16* __restrict__ Kh, const bf16* __restrict__ Kl,
    const bf16* __restrict__ Vth, const bf16* __restrict__ Vtl,
    const int* __restrict__ mask,
    bf16* __restrict__ ctxhi, bf16* __restrict__ ctxlo)
{
    extern __shared__ char smem[];
    uint32_t sb = smem_u32(smem);
    int t = threadIdx.x, lane = t & 31, w = t >> 5;
    int hh = blockIdx.y, b = blockIdx.z;
    int bh = b * HEADS + hh;
    int q0 = blockIdx.x * 64;
    const int NT = SEQ / 64;

    int aRow  = lane & 15;
    int aColB = ((lane >> 4) & 1) * 16;
    int bRow  = ((lane >> 4) & 1) * 8 + (lane & 7);
    int bColB = ((lane >> 3) & 1) * 16;

    // ---- Q tile load (once) ----
    {
        size_t qbase = ((size_t)bh * SEQ + q0) * DK;
        #pragma unroll
        for (int i = 0; i < 4; i++) {
            int idx = t + i * 128;            // 0..511
            int r = idx >> 3, ch = idx & 7;
            uint32_t d = sb + r * FP + ch * 16;
            size_t g = qbase + (size_t)r * DK + ch * 8;
            CPASYNC16(d,       Qh + g);
            CPASYNC16(d + FQT, Ql + g);
        }
    }
    auto load_stage = [&](int c){
        uint32_t st = sb + FST0 + (c & 1) * FSSZ;
        int kv0 = c * 64;
        size_t kbase = ((size_t)bh * SEQ + kv0) * DK;
        size_t vbase = (size_t)bh * DK * SEQ + kv0;
        #pragma unroll
        for (int i = 0; i < 4; i++) {
            int idx = t + i * 128;
            int r = idx >> 3, ch = idx & 7;
            uint32_t d = st + r * FP + ch * 16;
            CPASYNC16(d + FKH, Kh  + kbase + (size_t)r * DK + ch * 8);
            CPASYNC16(d + FKL, Kl  + kbase + (size_t)r * DK + ch * 8);
            CPASYNC16(d + FVH, Vth + vbase + (size_t)r * SEQ + ch * 8);
            CPASYNC16(d + FVL, Vtl + vbase + (size_t)r * SEQ + ch * 8);
        }
        if (t < 16) CPASYNC16(st + FMK + t * 16, mask + (size_t)b * SEQ + kv0 + t * 4);
    };

    load_stage(0); CPCOMMIT();
    load_stage(1); CPCOMMIT();

    uint32_t Qfh[4][4], Qfl[4][4];
    float oacc[8][4];
    #pragma unroll
    for (int i = 0; i < 8; i++)
        #pragma unroll
        for (int j = 0; j < 4; j++) oacc[i][j] = 0.f;
    float m0 = -1e30f, m1 = -1e30f, l0 = 0.f, l1 = 0.f;

    for (int c = 0; c < NT; c++) {
        CPWAIT1();
        __syncthreads();
        if (c == 0) {
            #pragma unroll
            for (int kc = 0; kc < 4; kc++) {
                uint32_t off = sb + (uint32_t)((w * 16 + aRow) * FP + kc * 32 + aColB);
                ldsm4(Qfh[kc], off);
                ldsm4(Qfl[kc], off + FQT);
            }
        }
        uint32_t st = sb + FST0 + (c & 1) * FSSZ;

        // ---- S = Q @ K^T (16x64 per warp) ----
        float sacc[8][4];
        #pragma unroll
        for (int i = 0; i < 8; i++)
            #pragma unroll
            for (int j = 0; j < 4; j++) sacc[i][j] = 0.f;
        #pragma unroll
        for (int kc = 0; kc < 4; kc++) {
            #pragma unroll
            for (int np = 0; np < 4; np++) {
                uint32_t off = (uint32_t)((np * 16 + bRow) * FP + kc * 32 + bColB);
                uint32_t rh[4], rl[4];
                ldsm4(rh, st + FKH + off);
                ldsm4(rl, st + FKL + off);
                mma16816s(sacc[2*np],   Qfh[kc], rh[0], rh[1]);
                mma16816s(sacc[2*np],   Qfh[kc], rl[0], rl[1]);
                mma16816s(sacc[2*np],   Qfl[kc], rh[0], rh[1]);
                mma16816s(sacc[2*np+1], Qfh[kc], rh[2], rh[3]);
                mma16816s(sacc[2*np+1], Qfh[kc], rl[2], rl[3]);
                mma16816s(sacc[2*np+1], Qfl[kc], rh[2], rh[3]);
            }
        }

        // ---- mask + online softmax ----
        const int* mk = (const int*)(smem + FST0 + (c & 1) * FSSZ + FMK);
        float mx0 = -1e30f, mx1 = -1e30f;
        #pragma unroll
        for (int nt = 0; nt < 8; nt++) {
            int col = nt * 8 + (lane & 3) * 2;
            float mv0 = mk[col]     ? 0.f : -1e9f;
            float mv1 = mk[col + 1] ? 0.f : -1e9f;
            sacc[nt][0] += mv0; sacc[nt][1] += mv1;
            sacc[nt][2] += mv0; sacc[nt][3] += mv1;
            mx0 = fmaxf(mx0, fmaxf(sacc[nt][0], sacc[nt][1]));
            mx1 = fmaxf(mx1, fmaxf(sacc[nt][2], sacc[nt][3]));
        }
        #pragma unroll
        for (int off = 1; off <= 2; off <<= 1) {
            mx0 = fmaxf(mx0, __shfl_xor_sync(0xffffffffu, mx0, off));
            mx1 = fmaxf(mx1, __shfl_xor_sync(0xffffffffu, mx1, off));
        }
        float nm0 = fmaxf(m0, mx0), nm1 = fmaxf(m1, mx1);
        float cr0 = __expf(m0 - nm0), cr1 = __expf(m1 - nm1);
        m0 = nm0; m1 = nm1;
        float rs0 = 0.f, rs1 = 0.f;
        #pragma unroll
        for (int nt = 0; nt < 8; nt++) {
            sacc[nt][0] = __expf(sacc[nt][0] - nm0);
            sacc[nt][1] = __expf(sacc[nt][1] - nm0);
            sacc[nt][2] = __expf(sacc[nt][2] - nm1);
            sacc[nt][3] = __expf(sacc[nt][3] - nm1);
            rs0 += sacc[nt][0] + sacc[nt][1];
            rs1 += sacc[nt][2] + sacc[nt][3];
            oacc[nt][0] *= cr0; oacc[nt][1] *= cr0;
            oacc[nt][2] *= cr1; oacc[nt][3] *= cr1;
        }
        #pragma unroll
        for (int off = 1; off <= 2; off <<= 1) {
            rs0 += __shfl_xor_sync(0xffffffffu, rs0, off);
            rs1 += __shfl_xor_sync(0xffffffffu, rs1, off);
        }
        l0 = l0 * cr0 + rs0;
        l1 = l1 * cr1 + rs1;

        // ---- P fragments (C-layout == A-layout identity) ----
        uint32_t Pah[4][4], Pal[4][4];
        #pragma unroll
        for (int kc = 0; kc < 4; kc++) {
            #pragma unroll
            for (int half = 0; half < 2; half++) {
                int nt = 2 * kc + half;
                float p0 = sacc[nt][0], p1 = sacc[nt][1];
                float p2 = sacc[nt][2], p3 = sacc[nt][3];
                bf16 h0 = __float2bfloat16(p0), h1 = __float2bfloat16(p1);
                bf16 h2 = __float2bfloat16(p2), h3 = __float2bfloat16(p3);
                Pah[kc][0 + 2*half] = *(uint32_t*)&(__nv_bfloat162&)*(__nv_bfloat162[]){__halves2bfloat162(h0, h1)};
                Pah[kc][1 + 2*half] = *(uint32_t*)&(__nv_bfloat162&)*(__nv_bfloat162[]){__halves2bfloat162(h2, h3)};
                Pal[kc][0 + 2*half] = packbf2(p0 - __bfloat162float(h0), p1 - __bfloat162float(h1));
                Pal[kc][1 + 2*half] = packbf2(p2 - __bfloat162float(h2), p3 - __bfloat162float(h3));
            }
        }

        // ---- O += P @ V (Vt rows = dk, cols = kv) ----
        #pragma unroll
        for (int kc = 0; kc < 4; kc++) {
            #pragma unroll
            for (int np = 0; np < 4; np++) {
                uint32_t off = (uint32_t)((np * 16 + bRow) * FP + kc * 32 + bColB);
                uint32_t vh[4], vl[4];
                ldsm4(vh, st + FVH + off);
                ldsm4(vl, st + FVL + off);
                mma16816s(oacc[2*np],   Pah[kc], vh[0], vh[1]);
                mma16816s(oacc[2*np],   Pah[kc], vl[0], vl[1]);
                mma16816s(oacc[2*np],   Pal[kc], vh[0], vh[1]);
                mma16816s(oacc[2*np+1], Pah[kc], vh[2], vh[3]);
                mma16816s(oacc[2*np+1], Pah[kc], vl[2], vl[3]);
                mma16816s(oacc[2*np+1], Pal[kc], vh[2], vh[3]);
            }
        }

        __syncthreads();
        if (c + 2 < NT) load_stage(c + 2);
        CPCOMMIT();
    }

    // ---- epilogue ----
    float inv0 = 1.f / l0, inv1 = 1.f / l1;
    int r0 = q0 + w * 16 + (lane >> 2);
    size_t tok0 = (size_t)b * SEQ + r0;
    #pragma unroll
    for (int nt = 0; nt < 8; nt++) {
        int col = hh * DK + nt * 8 + (lane & 3) * 2;
        bf16 h0, h1, h2, h3, e0, e1, e2, e3;
        f2hilo(oacc[nt][0] * inv0, h0, e0);
        f2hilo(oacc[nt][1] * inv0, h1, e1);
        f2hilo(oacc[nt][2] * inv1, h2, e2);
        f2hilo(oacc[nt][3] * inv1, h3, e3);
        *(__nv_bfloat162*)(ctxhi + tok0 * D_MODEL + col)       = __halves2bfloat162(h0, h1);
        *(__nv_bfloat162*)(ctxhi + (tok0 + 8) * D_MODEL + col) = __halves2bfloat162(h2, h3);
        *(__nv_bfloat162*)(ctxlo + tok0 * D_MODEL + col)       = __halves2bfloat162(e0, e1);
        *(__nv_bfloat162*)(ctxlo + (tok0 + 8) * D_MODEL + col) = __halves2bfloat162(e2, e3);
    }
}

// ---------------- out = LayerNorm(a + r); optionally also hi/lo ---------------
template<bool HILO>
__global__ __launch_bounds__(256) void add_ln(
    const float* __restrict__ a, const float* __restrict__ r,
    const float* __restrict__ g, const float* __restrict__ beta,
    float* __restrict__ out, bf16* __restrict__ ohi, bf16* __restrict__ olo)
{
    int row = blockIdx.x;
    int t = threadIdx.x;
    __shared__ float red0[8], red1[8];

    const float* ap = a + (size_t)row * D_MODEL;
    const float* rp = r + (size_t)row * D_MODEL;
    float x[4];
    float s = 0.f, s2 = 0.f;
    #pragma unroll
    for (int i = 0; i < 4; i++) {
        int c = t + i * 256;
        x[i] = ap[c] + rp[c];
        s += x[i]; s2 += x[i] * x[i];
    }
    #pragma unroll
    for (int off = 16; off > 0; off >>= 1) {
        s  += __shfl_xor_sync(0xffffffffu, s,  off);
        s2 += __shfl_xor_sync(0xffffffffu, s2, off);
    }
    int wid = t >> 5;
    if ((t & 31) == 0) { red0[wid] = s; red1[wid] = s2; }
    __syncthreads();
    s = 0.f; s2 = 0.f;
    #pragma unroll
    for (int w = 0; w < 8; w++) { s += red0[w]; s2 += red1[w]; }

    float mean = s * (1.f / D_MODEL);
    float var = s2 * (1.f / D_MODEL) - mean * mean;
    float inv = rsqrtf(var + 1e-5f);
    #pragma unroll
    for (int i = 0; i < 4; i++) {
        int c = t + i * 256;
        float y = (x[i] - mean) * inv * g[c] + beta[c];
        out[(size_t)row * D_MODEL + c] = y;
        if (HILO) {
            bf16 h, l; f2hilo(y, h, l);
            ohi[(size_t)row * D_MODEL + c] = h;
            olo[(size_t)row * D_MODEL + c] = l;
        }
    }
}

// ---------------- launch --------------------------------------------------------
extern "C" void kernel_launch(void* const* d_in, const int* in_sizes, int n_in,
                              void* d_out, int out_size)
{
    const float* x     = (const float*)d_in[0];
    const int*   mask  = (const int*)  d_in[1];
    const float* Wq    = (const float*)d_in[2];
    const float* bq    = (const float*)d_in[3];
    const float* Wk    = (const float*)d_in[4];
    const float* bk    = (const float*)d_in[5];
    const float* Wv    = (const float*)d_in[6];
    const float* bv    = (const float*)d_in[7];
    const float* Wo    = (const float*)d_in[8];
    const float* bo    = (const float*)d_in[9];
    const float* ln1_g = (const float*)d_in[10];
    const float* ln1_b = (const float*)d_in[11];
    const float* ln2_g = (const float*)d_in[12];
    const float* ln2_b = (const float*)d_in[13];
    const float* W1    = (const float*)d_in[14];
    const float* b1    = (const float*)d_in[15];
    const float* W2    = (const float*)d_in[16];
    const float* b2    = (const float*)d_in[17];

    bf16 *pxhi, *pxlo, *pWqh, *pWql, *pcxh, *pcxl, *pWoh, *pWol;
    bf16 *phhi, *phlo, *pW1h, *pW1l, *pW2h, *pW2l, *pf1h, *pf1l;
    bf16 *pqh, *pql, *pkh, *pkl, *pvth, *pvtl;
    float *pbqkv, *pqkv, *patt, *ph, *pff2;
    cudaGetSymbolAddress((void**)&pxhi, g_xhi);   cudaGetSymbolAddress((void**)&pxlo, g_xlo);
    cudaGetSymbolAddress((void**)&pWqh, g_Wqkv_hi); cudaGetSymbolAddress((void**)&pWql, g_Wqkv_lo);
    cudaGetSymbolAddress((void**)&pbqkv, g_bqkv); cudaGetSymbolAddress((void**)&pqkv, g_qkv);
    cudaGetSymbolAddress((void**)&pqh, g_qh);     cudaGetSymbolAddress((void**)&pql, g_ql);
    cudaGetSymbolAddress((void**)&pkh, g_kh);     cudaGetSymbolAddress((void**)&pkl, g_kl);
    cudaGetSymbolAddress((void**)&pvth, g_vth);   cudaGetSymbolAddress((void**)&pvtl, g_vtl);
    cudaGetSymbolAddress((void**)&pcxh, g_ctxhi); cudaGetSymbolAddress((void**)&pcxl, g_ctxlo);
    cudaGetSymbolAddress((void**)&pWoh, g_Wo_hi); cudaGetSymbolAddress((void**)&pWol, g_Wo_lo);
    cudaGetSymbolAddress((void**)&patt, g_att);   cudaGetSymbolAddress((void**)&ph, g_h);
    cudaGetSymbolAddress((void**)&phhi, g_hhi);   cudaGetSymbolAddress((void**)&phlo, g_hlo);
    cudaGetSymbolAddress((void**)&pW1h, g_W1_hi); cudaGetSymbolAddress((void**)&pW1l, g_W1_lo);
    cudaGetSymbolAddress((void**)&pW2h, g_W2_hi); cudaGetSymbolAddress((void**)&pW2l, g_W2_lo);
    cudaGetSymbolAddress((void**)&pf1h, g_ff1hi); cudaGetSymbolAddress((void**)&pf1l, g_ff1lo);
    cudaGetSymbolAddress((void**)&pff2, g_ff2);

    cudaFuncSetAttribute(gemm_mma<false, true, false>,
                         cudaFuncAttributeMaxDynamicSharedMemorySize, SMEM_GEMM);
    cudaFuncSetAttribute(gemm_mma<true, false, true>,
                         cudaFuncAttributeMaxDynamicSharedMemorySize, SMEM_GEMM);
    cudaFuncSetAttribute(flash_mma,
                         cudaFuncAttributeMaxDynamicSharedMemorySize, SMEM_FLASH);

    // weight/activation prep
    convert_x<<<(NTOK * D_MODEL + 255) / 256, 256>>>(x, pxhi, pxlo, NTOK * D_MODEL);
    pack_qkv_w<<<(3 * D_MODEL * D_MODEL + 255) / 256, 256>>>(Wq, Wk, Wv, bq, bk, bv);
    tconv<<<dim3(D_MODEL / 32, D_MODEL / 32), dim3(32, 32)>>>(Wo, pWoh, pWol, D_MODEL, D_MODEL);
    tconv<<<dim3(D_FF / 32,    D_MODEL / 32), dim3(32, 32)>>>(W1, pW1h, pW1l, D_MODEL, D_FF);
    tconv<<<dim3(D_MODEL / 32, D_FF / 32),    dim3(32, 32)>>>(W2, pW2h, pW2l, D_FF, D_MODEL);

    // qkv = x @ Wqkv + bqkv  (fp32 out)
    gemm_mma<false, true, false><<<dim3(3 * D_MODEL / 128, NTOK / 128), 256, SMEM_GEMM>>>(
        pxhi, pxlo, pWqh, pWql, pbqkv, pqkv, nullptr, nullptr, NTOK, 3 * D_MODEL, D_MODEL);

    // attention operand prep + HMMA flash attention -> ctx hi/lo
    prep_attn<<<dim3(SEQ / 32, DK / 32, BATCH * HEADS), dim3(32, 32)>>>(pqkv);
    flash_mma<<<dim3(SEQ / 64, HEADS, BATCH), 128, SMEM_FLASH>>>(
        pqh, pql, pkh, pkl, pvth, pvtl, mask, pcxh, pcxl);

    // att = ctx @ Wo + bo (fp32)
    gemm_mma<false, true, false><<<dim3(D_MODEL / 128, NTOK / 128), 256, SMEM_GEMM>>>(
        pcxh, pcxl, pWoh, pWol, bo, patt, nullptr, nullptr, NTOK, D_MODEL, D_MODEL);

    // h = LN(x + att)  (fp32 + hi/lo)
    add_ln<true><<<NTOK, 256>>>(patt, x, ln1_g, ln1_b, ph, phhi, phlo);

    // ff1 = relu(h @ W1 + b1)  (hi/lo only)
    gemm_mma<true, false, true><<<dim3(D_FF / 128, NTOK / 128), 256, SMEM_GEMM>>>(
        phhi, phlo, pW1h, pW1l, b1, nullptr, pf1h, pf1l, NTOK, D_FF, D_MODEL);

    // ff2 = ff1 @ W2 + b2 (fp32)
    gemm_mma<false, true, false><<<dim3(D_MODEL / 128, NTOK / 128), 256, SMEM_GEMM>>>(
        pf1h, pf1l, pW2h, pW2l, b2, pff2, nullptr, nullptr, NTOK, D_MODEL, D_FF);

    // out = LN(h + ff2)
    add_ln<false><<<NTOK, 256>>>(pff2, ph, ln2_g, ln2_b, (float*)d_out, nullptr, nullptr);
}